// round 1
// baseline (speedup 1.0000x reference)
#include <cuda_runtime.h>
#include <math.h>
#include <stdint.h>

// ---------------- Problem constants ----------------
#define BB      8
#define SEQLEN  4096
#define CINC    7
#define DMOD    512
#define NLAY    4
#define PLEN    16
#define NPATCH  256            // SEQ/PL
#define NST     16             // NS
#define DCONV   4
#define DINNER  1024           // EXP*DM
#define DTRANK  32             // (DM+15)/16
#define MROWS   (BB*NPATCH)    // 2048 token rows
#define KPATCH  (CINC*PLEN)    // 112
#define HCD     64
#define HPRED   96
#define KSPLIT  32             // head split-K slices
#define KFLAT   (NPATCH*DMOD)  // 131072

// ---------------- Scratch (static device globals; no runtime alloc) ----------------
__device__ float g_h  [MROWS*DMOD];       // residual stream
__device__ float g_ln [MROWS*DMOD];       // post-LN activations
__device__ float g_pn [MROWS*KPATCH];     // normalized patches
__device__ float g_xz [MROWS*2*DINNER];   // W_in output (xi | z)
__device__ float g_xc [MROWS*DINNER];     // conv+silu output
__device__ float g_dbl[MROWS*64];         // dt | B | C
__device__ float g_pre[MROWS*DINNER];     // delta pre-activation
__device__ float g_y  [MROWS*DINNER];     // gated scan output
__device__ float g_part[KSPLIT*BB*128];   // head split-K partials

// =====================================================================
// Tiled SGEMM (NT layout): C[M,N] = A[M,K] * W[N,K]^T (+bias / +=C)
// EPI: 0=store, 1=store+bias[n], 2=accumulate into C (residual add)
// =====================================================================
template<int BM, int BN, int TM, int TN, int EPI>
__global__ void __launch_bounds__(256)
sgemm_nt(int M, int N, int K,
         const float* __restrict__ A, int lda,
         const float* __restrict__ W, int ldw,
         const float* __restrict__ bias,
         float* __restrict__ C, int ldc)
{
    constexpr int BK = 16;
    constexpr int NT = (BM/TM)*(BN/TN);      // must be 256
    __shared__ float As[BK][BM+4];
    __shared__ float Ws[BK][BN+4];

    const int tid = threadIdx.x;
    const int tx  = tid % (BN/TN);
    const int ty  = tid / (BN/TN);
    const int m0  = blockIdx.y * BM;
    const int n0  = blockIdx.x * BN;

    float acc[TM][TN];
    #pragma unroll
    for (int i = 0; i < TM; i++)
        #pragma unroll
        for (int j = 0; j < TN; j++) acc[i][j] = 0.f;

    for (int k0 = 0; k0 < K; k0 += BK) {
        // load A tile (BM x BK) transposed into As[k][m]
        #pragma unroll
        for (int i = 0; i < (BM*BK)/(NT*4); i++) {
            int lid = tid + i*NT;          // float4 index
            int r   = lid / (BK/4);
            int c4  = lid % (BK/4);
            float4 v = *(const float4*)&A[(m0 + r)*lda + k0 + c4*4];
            As[c4*4+0][r] = v.x; As[c4*4+1][r] = v.y;
            As[c4*4+2][r] = v.z; As[c4*4+3][r] = v.w;
        }
        // load W tile (BN x BK) transposed into Ws[k][n]
        #pragma unroll
        for (int i = 0; i < (BN*BK)/(NT*4); i++) {
            int lid = tid + i*NT;
            int r   = lid / (BK/4);
            int c4  = lid % (BK/4);
            float4 v = *(const float4*)&W[(n0 + r)*ldw + k0 + c4*4];
            Ws[c4*4+0][r] = v.x; Ws[c4*4+1][r] = v.y;
            Ws[c4*4+2][r] = v.z; Ws[c4*4+3][r] = v.w;
        }
        __syncthreads();

        #pragma unroll
        for (int kk = 0; kk < BK; kk++) {
            float af[TM], bf[TN];
            #pragma unroll
            for (int i = 0; i < TM; i += 4) {
                float4 v = *(const float4*)&As[kk][ty*TM + i];
                af[i] = v.x; af[i+1] = v.y; af[i+2] = v.z; af[i+3] = v.w;
            }
            #pragma unroll
            for (int j = 0; j < TN; j += 4) {
                float4 v = *(const float4*)&Ws[kk][tx*TN + j];
                bf[j] = v.x; bf[j+1] = v.y; bf[j+2] = v.z; bf[j+3] = v.w;
            }
            #pragma unroll
            for (int i = 0; i < TM; i++)
                #pragma unroll
                for (int j = 0; j < TN; j++)
                    acc[i][j] = fmaf(af[i], bf[j], acc[i][j]);
        }
        __syncthreads();
    }

    // epilogue
    #pragma unroll
    for (int i = 0; i < TM; i++) {
        int m = m0 + ty*TM + i;
        #pragma unroll
        for (int j = 0; j < TN; j += 4) {
            int n = n0 + tx*TN + j;
            float4 r;
            r.x = acc[i][j];   r.y = acc[i][j+1];
            r.z = acc[i][j+2]; r.w = acc[i][j+3];
            if (EPI == 1) {
                r.x += bias[n];   r.y += bias[n+1];
                r.z += bias[n+2]; r.w += bias[n+3];
            }
            if (EPI == 2) {
                float4 c = *(const float4*)&C[m*ldc + n];
                r.x += c.x; r.y += c.y; r.z += c.z; r.w += c.w;
            }
            *(float4*)&C[m*ldc + n] = r;
        }
    }
}

// =====================================================================
// Input layernorm over CIN=7 + scatter into patch-GEMM layout
// g_pn[(b*NP+n)*112 + c*16 + p] = LN(x)[b, n*16+p, c]
// =====================================================================
__global__ void k_patchnorm(const float* __restrict__ x,
                            const float* __restrict__ gam,
                            const float* __restrict__ bet,
                            float* __restrict__ pn)
{
    int idx = blockIdx.x*blockDim.x + threadIdx.x;
    if (idx >= BB*SEQLEN) return;
    int b = idx / SEQLEN, s = idx % SEQLEN;
    const float* xp = x + idx*CINC;
    float sum = 0.f;
    #pragma unroll
    for (int c = 0; c < CINC; c++) sum += xp[c];
    float m = sum * (1.f/CINC);
    float var = 0.f;
    #pragma unroll
    for (int c = 0; c < CINC; c++) { float d = xp[c]-m; var = fmaf(d,d,var); }
    var *= (1.f/CINC);
    float inv = rsqrtf(var + 1e-5f);
    int n = s / PLEN, p = s % PLEN;
    float* o = pn + (b*NPATCH + n)*KPATCH;
    #pragma unroll
    for (int c = 0; c < CINC; c++)
        o[c*PLEN + p] = (xp[c]-m)*inv*gam[c] + bet[c];
}

// =====================================================================
// Row layernorm, width DM=512. One block (128 thr) per row.
// =====================================================================
__global__ void __launch_bounds__(128)
k_ln(const float* __restrict__ in, float* __restrict__ out,
     const float* __restrict__ gam, const float* __restrict__ bet)
{
    const int row = blockIdx.x;
    const float* x = in + row*DMOD;
    float s = 0.f, ss = 0.f;
    #pragma unroll
    for (int i = threadIdx.x; i < DMOD; i += 128) {
        float v = x[i]; s += v; ss = fmaf(v, v, ss);
    }
    __shared__ float sh1[4], sh2[4];
    #pragma unroll
    for (int o = 16; o > 0; o >>= 1) {
        s  += __shfl_down_sync(0xffffffffu, s,  o);
        ss += __shfl_down_sync(0xffffffffu, ss, o);
    }
    if ((threadIdx.x & 31) == 0) { sh1[threadIdx.x>>5] = s; sh2[threadIdx.x>>5] = ss; }
    __syncthreads();
    __shared__ float smean, sinv;
    if (threadIdx.x == 0) {
        float ts  = sh1[0]+sh1[1]+sh1[2]+sh1[3];
        float tss = sh2[0]+sh2[1]+sh2[2]+sh2[3];
        float m   = ts * (1.f/DMOD);
        float var = tss * (1.f/DMOD) - m*m;
        smean = m; sinv = rsqrtf(var + 1e-5f);
    }
    __syncthreads();
    float m = smean, inv = sinv;
    float* o = out + row*DMOD;
    #pragma unroll
    for (int i = threadIdx.x; i < DMOD; i += 128)
        o[i] = (x[i]-m)*inv*gam[i] + bet[i];
}

// =====================================================================
// Depthwise causal conv (DC=4) + silu.  xi = xz[..., :DI]
// =====================================================================
__global__ void k_conv(const float* __restrict__ xz,
                       const float* __restrict__ cw,
                       const float* __restrict__ cb,
                       float* __restrict__ xc)
{
    int idx = blockIdx.x*blockDim.x + threadIdx.x;
    if (idx >= MROWS*DINNER) return;
    int d  = idx % DINNER;
    int bl = idx / DINNER;
    int l  = bl % NPATCH;
    int b  = bl / NPATCH;
    const float4 w = *(const float4*)(cw + d*4);
    float acc = cb[d];
    int base = (b*NPATCH)*2*DINNER + d;
    if (l >= 3) acc = fmaf(xz[base + (l-3)*2*DINNER], w.x, acc);
    if (l >= 2) acc = fmaf(xz[base + (l-2)*2*DINNER], w.y, acc);
    if (l >= 1) acc = fmaf(xz[base + (l-1)*2*DINNER], w.z, acc);
    acc = fmaf(xz[base + l*2*DINNER], w.w, acc);
    xc[idx] = acc / (1.f + __expf(-acc));           // silu
}

// =====================================================================
// Selective scan, fused with output gating.
// One thread per (b,d): 16-state recurrence in registers.
// Uses exp(-softplus(x)) == sigmoid(-x); dA_n = q^(n+1) when A[d,n]=-(n+1)
// (checked per-thread; general __expf fallback otherwise).
// =====================================================================
__global__ void __launch_bounds__(128)
k_scan(const float* __restrict__ pre, const float* __restrict__ xc,
       const float* __restrict__ xz,  const float* __restrict__ dbl,
       const float* __restrict__ A_log, const float* __restrict__ Dskip,
       float* __restrict__ y)
{
    const int d = blockIdx.x*128 + threadIdx.x;
    const int b = blockIdx.y;

    float a[NST];
    bool structured = true;
    #pragma unroll
    for (int n = 0; n < NST; n++) {
        a[n] = -__expf(A_log[d*NST + n]);
        structured = structured && (fabsf(a[n] + (float)(n+1)) <= 1e-4f*(float)(n+1));
    }
    const float Dv = Dskip[d];
    float h[NST];
    #pragma unroll
    for (int n = 0; n < NST; n++) h[n] = 0.f;

    __shared__ float sBC[16][32];

    for (int tt = 0; tt < NPATCH; tt += 16) {
        __syncthreads();
        {   // stage B|C for 16 timesteps (512 floats, coalesced)
            int r = threadIdx.x / 8, c = threadIdx.x % 8;
            float4 v = *(const float4*)&dbl[(b*NPATCH + tt + r)*64 + 32 + c*4];
            *(float4*)&sBC[r][c*4] = v;
        }
        __syncthreads();

        for (int t2 = 0; t2 < 16; t2++) {
            int base = b*NPATCH + tt + t2;
            float xv  = pre[base*DINNER + d];
            float xcv = xc [base*DINNER + d];
            float zv  = xz [base*2*DINNER + DINNER + d];

            // q = sigmoid(-xv) = exp(-softplus(xv)); delta = softplus(xv)
            float q, delta;
            if (xv > 0.f) {
                float e = __expf(-xv);
                q = e / (1.f + e);
                delta = xv + __logf(1.f + e);
            } else {
                float e = __expf(xv);
                q = 1.f / (1.f + e);
                delta = __logf(1.f + e);
            }

            float pw[NST];
            if (structured) {
                float q2 = q*q, q4 = q2*q2, q8 = q4*q4;
                pw[0]=q;      pw[1]=q2;       pw[2]=q2*q;     pw[3]=q4;
                pw[4]=q4*q;   pw[5]=q4*q2;    pw[6]=q4*pw[2]; pw[7]=q8;
                pw[8]=q8*q;   pw[9]=q8*q2;    pw[10]=q8*pw[2];pw[11]=q8*q4;
                pw[12]=q8*pw[4]; pw[13]=q8*pw[5]; pw[14]=q8*pw[6]; pw[15]=q8*q8;
            } else {
                #pragma unroll
                for (int n = 0; n < NST; n++) pw[n] = __expf(delta*a[n]);
            }

            float dx = delta * xcv;
            float acc = 0.f;
            #pragma unroll
            for (int n = 0; n < NST; n++) {
                h[n] = fmaf(pw[n], h[n], dx * sBC[t2][n]);
                acc  = fmaf(h[n], sBC[t2][16+n], acc);
            }
            float sz = zv / (1.f + __expf(-zv));
            y[base*DINNER + d] = (acc + xcv*Dv) * sz;
        }
    }
}

// =====================================================================
// Head GEMM1 split-K: partials[ks][b*128+j] (deterministic, no atomics)
// grid = (8 j-tiles of 16, 32 K-slices of 4096); 128 threads
// =====================================================================
__global__ void __launch_bounds__(128)
k_head1(const float* __restrict__ hin, const float* __restrict__ W,
        float* __restrict__ part)
{
    const int j0 = blockIdx.x * 16;
    const int k0 = blockIdx.y * (KFLAT / KSPLIT);
    const int tid = threadIdx.x;
    const int bb = tid / 16, jj = tid % 16;
    __shared__ float shh[BB][129];
    __shared__ float shw[16][129];
    float acc = 0.f;
    for (int kc = 0; kc < KFLAT/KSPLIT; kc += 128) {
        int k = k0 + kc + tid;
        #pragma unroll
        for (int i = 0; i < BB; i++)  shh[i][tid] = hin[i*KFLAT + k];
        #pragma unroll
        for (int i = 0; i < 16; i++)  shw[i][tid] = W[(j0 + i)*KFLAT + k];
        __syncthreads();
        #pragma unroll 8
        for (int k2 = 0; k2 < 128; k2++)
            acc = fmaf(shh[bb][k2], shw[jj][k2], acc);
        __syncthreads();
    }
    part[blockIdx.y*(BB*128) + bb*128 + j0 + jj] = acc;
}

// =====================================================================
// Head: reduce partials, bias+gelu(exact), final tiny GEMM -> out (8,96)
// grid = 8 (one block per b), 128 threads
// =====================================================================
__global__ void __launch_bounds__(128)
k_head2(const float* __restrict__ part, const float* __restrict__ hb1,
        const float* __restrict__ hW2,  const float* __restrict__ hb2,
        float* __restrict__ out)
{
    const int b = blockIdx.x;
    const int tid = threadIdx.x;
    __shared__ float g[128];
    float v = 0.f;
    #pragma unroll
    for (int ks = 0; ks < KSPLIT; ks++)
        v += part[ks*(BB*128) + b*128 + tid];
    v += hb1[tid];
    g[tid] = 0.5f * v * (1.f + erff(v * 0.70710678118654752f));
    __syncthreads();
    if (tid < HPRED) {
        float acc = hb2[tid];
        #pragma unroll 16
        for (int j = 0; j < 128; j++)
            acc = fmaf(g[j], hW2[tid*128 + j], acc);
        out[b*HPRED + tid] = acc;
    }
}

// =====================================================================
// Launch
// =====================================================================
static float* symaddr(const void* sym)
{
    void* p = nullptr;
    cudaGetSymbolAddress(&p, sym);
    return (float*)p;
}

extern "C" void kernel_launch(void* const* d_in, const int* in_sizes, int n_in,
                              void* d_out, int out_size)
{
    const float* x      = (const float*)d_in[0];
    const float* in_g   = (const float*)d_in[1];
    const float* in_b   = (const float*)d_in[2];
    const float* pe_W   = (const float*)d_in[3];
    const float* pe_b   = (const float*)d_in[4];
    const float* ln_g   = (const float*)d_in[5];
    const float* ln_b   = (const float*)d_in[6];
    const float* W_in   = (const float*)d_in[7];
    const float* conv_W = (const float*)d_in[8];
    const float* conv_b = (const float*)d_in[9];
    const float* W_x    = (const float*)d_in[10];
    const float* W_dt   = (const float*)d_in[11];
    const float* b_dt   = (const float*)d_in[12];
    const float* A_log  = (const float*)d_in[13];
    const float* Dskip  = (const float*)d_in[14];
    const float* W_out  = (const float*)d_in[15];
    const float* fn_g   = (const float*)d_in[16];
    const float* fn_b   = (const float*)d_in[17];
    const float* hW1    = (const float*)d_in[18];
    const float* hb1    = (const float*)d_in[19];
    const float* hW2    = (const float*)d_in[20];
    const float* hb2    = (const float*)d_in[21];

    float* ph   = symaddr(g_h);
    float* pln  = symaddr(g_ln);
    float* ppn  = symaddr(g_pn);
    float* pxz  = symaddr(g_xz);
    float* pxc  = symaddr(g_xc);
    float* pdbl = symaddr(g_dbl);
    float* ppre = symaddr(g_pre);
    float* py   = symaddr(g_y);
    float* ppart= symaddr(g_part);

    // 1) input LN + patch layout
    k_patchnorm<<<(BB*SEQLEN + 255)/256, 256>>>(x, in_g, in_b, ppn);

    // 2) patch embedding: h = pn @ pe_W^T + pe_b   (2048 x 512, K=112)
    sgemm_nt<128,128,8,8,1><<<dim3(DMOD/128, MROWS/128), 256>>>(
        MROWS, DMOD, KPATCH, ppn, KPATCH, pe_W, KPATCH, pe_b, ph, DMOD);

    // 3) Mamba layers
    for (int i = 0; i < NLAY; i++) {
        k_ln<<<MROWS, 128>>>(ph, pln, ln_g + i*DMOD, ln_b + i*DMOD);

        // xz = ln @ W_in^T  (2048 x 2048, K=512)
        sgemm_nt<128,128,8,8,0><<<dim3(2*DINNER/128, MROWS/128), 256>>>(
            MROWS, 2*DINNER, DMOD, pln, DMOD,
            W_in + (size_t)i*2*DINNER*DMOD, DMOD, nullptr, pxz, 2*DINNER);

        // depthwise causal conv + silu
        k_conv<<<(MROWS*DINNER + 255)/256, 256>>>(
            pxz, conv_W + (size_t)i*DINNER*DCONV, conv_b + (size_t)i*DINNER, pxc);

        // dbl = xc @ W_x^T  (2048 x 64, K=1024)
        sgemm_nt<64,64,4,4,0><<<dim3(1, MROWS/64), 256>>>(
            MROWS, 64, DINNER, pxc, DINNER,
            W_x + (size_t)i*64*DINNER, DINNER, nullptr, pdbl, 64);

        // pre = dt @ W_dt^T + b_dt  (2048 x 1024, K=32; A has lda=64)
        sgemm_nt<128,128,8,8,1><<<dim3(DINNER/128, MROWS/128), 256>>>(
            MROWS, DINNER, DTRANK, pdbl, 64,
            W_dt + (size_t)i*DINNER*DTRANK, DTRANK, b_dt + (size_t)i*DINNER,
            ppre, DINNER);

        // fused selective scan + gating
        k_scan<<<dim3(DINNER/128, BB), 128>>>(
            ppre, pxc, pxz, pdbl,
            A_log + (size_t)i*DINNER*NST, Dskip + (size_t)i*DINNER, py);

        // h += y @ W_out^T  (2048 x 512, K=1024), residual accumulate
        sgemm_nt<128,128,8,8,2><<<dim3(DMOD/128, MROWS/128), 256>>>(
            MROWS, DMOD, DINNER, py, DINNER,
            W_out + (size_t)i*DMOD*DINNER, DINNER, nullptr, ph, DMOD);
    }

    // 4) final LN
    k_ln<<<MROWS, 128>>>(ph, pln, fn_g, fn_b);

    // 5) head
    k_head1<<<dim3(8, KSPLIT), 128>>>(pln, hW1, ppart);
    k_head2<<<BB, 128>>>(ppart, hb1, hW2, hb2, (float*)d_out);
}

// round 3
// speedup vs baseline: 1.4820x; 1.4820x over previous
#include <cuda_runtime.h>
#include <cuda_bf16.h>
#include <math.h>
#include <stdint.h>

// ---------------- Problem constants ----------------
#define BB      8
#define SEQLEN  4096
#define CINC    7
#define DMOD    512
#define NLAY    4
#define PLEN    16
#define NPATCH  256
#define NST     16
#define DCONV   4
#define DINNER  1024
#define DTRANK  32
#define MROWS   (BB*NPATCH)    // 2048
#define KPATCH  (CINC*PLEN)    // 112
#define HPRED   96
#define KSPLIT  32
#define KFLAT   (NPATCH*DMOD)  // 131072

// ---------------- Scratch ----------------
__device__ float g_h  [MROWS*DMOD];
__device__ float g_ln [MROWS*DMOD];
__device__ float g_pn [MROWS*KPATCH];
__device__ float g_xz [MROWS*2*DINNER];
__device__ float g_xc [MROWS*DINNER];
__device__ float g_dbl[MROWS*64];
__device__ float g_pre[MROWS*DINNER];
__device__ float g_y  [MROWS*DINNER];
__device__ float g_part[KSPLIT*BB*128];

// =====================================================================
// Low-level helpers
// =====================================================================
static __device__ __forceinline__ uint32_t smem_u32(const void* p) {
    uint32_t a;
    asm("{ .reg .u64 t; cvta.to.shared.u64 t, %1; cvt.u32.u64 %0, t; }"
        : "=r"(a) : "l"(p));
    return a;
}
static __device__ __forceinline__ void ldm_x4(uint32_t* r, uint32_t addr) {
    asm volatile("ldmatrix.sync.aligned.m8n8.x4.shared.b16 {%0,%1,%2,%3}, [%4];"
        : "=r"(r[0]), "=r"(r[1]), "=r"(r[2]), "=r"(r[3]) : "r"(addr));
}
static __device__ __forceinline__ void mma_bf16(float* c, const uint32_t* a,
                                                const uint32_t* b) {
    asm volatile(
        "mma.sync.aligned.m16n8k16.row.col.f32.bf16.bf16.f32 "
        "{%0,%1,%2,%3}, {%4,%5,%6,%7}, {%8,%9}, {%0,%1,%2,%3};"
        : "+f"(c[0]), "+f"(c[1]), "+f"(c[2]), "+f"(c[3])
        : "r"(a[0]), "r"(a[1]), "r"(a[2]), "r"(a[3]), "r"(b[0]), "r"(b[1]));
}
static __device__ __forceinline__ unsigned pk(__nv_bfloat16 a, __nv_bfloat16 b) {
    unsigned short ua = __bfloat16_as_ushort(a), ub = __bfloat16_as_ushort(b);
    return (unsigned)ua | ((unsigned)ub << 16);
}
static __device__ __forceinline__ void split4(float4 v, uint2& h, uint2& l) {
    __nv_bfloat16 h0 = __float2bfloat16(v.x), h1 = __float2bfloat16(v.y);
    __nv_bfloat16 h2 = __float2bfloat16(v.z), h3 = __float2bfloat16(v.w);
    __nv_bfloat16 l0 = __float2bfloat16(v.x - __bfloat162float(h0));
    __nv_bfloat16 l1 = __float2bfloat16(v.y - __bfloat162float(h1));
    __nv_bfloat16 l2 = __float2bfloat16(v.z - __bfloat162float(h2));
    __nv_bfloat16 l3 = __float2bfloat16(v.w - __bfloat162float(h3));
    h.x = pk(h0, h1); h.y = pk(h2, h3);
    l.x = pk(l0, l1); l.y = pk(l2, l3);
}

// =====================================================================
// bf16x3 mma.sync GEMM: C[M,N] = A[M,K] * W[N,K]^T   (fp32 in/out)
// CTA tile 128 x BN, BK=32, 8 warps (4m x 2n), warp tile 32 x BN/2.
// EPI: 0=store, 1=store+bias[n], 2=accumulate into C
// =====================================================================
template<int BN, int EPI>
__global__ void __launch_bounds__(256, 1)
mgemm(int M, int N, int K,
      const float* __restrict__ A, int lda,
      const float* __restrict__ W, int ldw,
      const float* __restrict__ bias,
      float* __restrict__ C, int ldc)
{
    constexpr int BM = 128, BK = 32, LDS = 40;
    constexpr int WN  = BN / 2;          // warp n extent
    constexpr int NT8 = WN / 8;          // 8-wide n tiles per warp
    constexpr int AF4 = 4;               // 128*8/256 float4 per thread
    constexpr int WF4 = BN / 32;         // BN*8/256

    __shared__ __align__(16) __nv_bfloat16 sAh[BM][LDS], sAl[BM][LDS];
    __shared__ __align__(16) __nv_bfloat16 sWh[BN][LDS], sWl[BN][LDS];

    const int tid  = threadIdx.x, lane = tid & 31, warp = tid >> 5;
    const int wm   = warp >> 1,   wn   = warp & 1;
    const int mB   = blockIdx.y * BM,  nB = blockIdx.x * BN;

    float acc[2][NT8][4];
    #pragma unroll
    for (int t = 0; t < 2; t++)
        #pragma unroll
        for (int j = 0; j < NT8; j++)
            #pragma unroll
            for (int r = 0; r < 4; r++) acc[t][j][r] = 0.f;

    const int nCh = (K + BK - 1) / BK;
    float4 rA[AF4], rW[WF4];

    // prologue: load chunk 0
    #pragma unroll
    for (int i = 0; i < AF4; i++) {
        int idx = i * 256 + tid, row = idx >> 3, c4 = idx & 7, kk = c4 * 4;
        rA[i] = (kk < K) ? *(const float4*)&A[(size_t)(mB + row) * lda + kk]
                         : make_float4(0.f, 0.f, 0.f, 0.f);
    }
    #pragma unroll
    for (int i = 0; i < WF4; i++) {
        int idx = i * 256 + tid, row = idx >> 3, c4 = idx & 7, kk = c4 * 4;
        rW[i] = (kk < K) ? *(const float4*)&W[(size_t)(nB + row) * ldw + kk]
                         : make_float4(0.f, 0.f, 0.f, 0.f);
    }

    for (int s = 0; s < nCh; s++) {
        __syncthreads();
        // convert + store to SMEM (hi / lo planes)
        #pragma unroll
        for (int i = 0; i < AF4; i++) {
            int idx = i * 256 + tid, row = idx >> 3, c4 = idx & 7;
            uint2 h, l; split4(rA[i], h, l);
            *(uint2*)&sAh[row][c4 * 4] = h;
            *(uint2*)&sAl[row][c4 * 4] = l;
        }
        #pragma unroll
        for (int i = 0; i < WF4; i++) {
            int idx = i * 256 + tid, row = idx >> 3, c4 = idx & 7;
            uint2 h, l; split4(rW[i], h, l);
            *(uint2*)&sWh[row][c4 * 4] = h;
            *(uint2*)&sWl[row][c4 * 4] = l;
        }
        __syncthreads();

        // prefetch next chunk while computing
        if (s + 1 < nCh) {
            const int k0 = (s + 1) * BK;
            #pragma unroll
            for (int i = 0; i < AF4; i++) {
                int idx = i * 256 + tid, row = idx >> 3, c4 = idx & 7, kk = k0 + c4 * 4;
                rA[i] = (kk < K) ? *(const float4*)&A[(size_t)(mB + row) * lda + kk]
                                 : make_float4(0.f, 0.f, 0.f, 0.f);
            }
            #pragma unroll
            for (int i = 0; i < WF4; i++) {
                int idx = i * 256 + tid, row = idx >> 3, c4 = idx & 7, kk = k0 + c4 * 4;
                rW[i] = (kk < K) ? *(const float4*)&W[(size_t)(nB + row) * ldw + kk]
                                 : make_float4(0.f, 0.f, 0.f, 0.f);
            }
        }

        // compute: 2 x k16 steps, 3 bf16 passes each
        #pragma unroll
        for (int k16 = 0; k16 < 2; k16++) {
            uint32_t ah[2][4], al[2][4], wh[NT8][2], wl[NT8][2];
            const int arow = wm * 32 + (lane & 15);
            const int acol = k16 * 16 + (lane >> 4) * 8;
            ldm_x4(ah[0], smem_u32(&sAh[arow     ][acol]));
            ldm_x4(ah[1], smem_u32(&sAh[arow + 16][acol]));
            const int wrow = wn * WN + ((lane >> 4) << 3) + (lane & 7);
            const int wcol = k16 * 16 + ((lane >> 3) & 1) * 8;
            #pragma unroll
            for (int jp = 0; jp < NT8 / 2; jp++) {
                uint32_t tmp[4];
                ldm_x4(tmp, smem_u32(&sWh[wrow + jp * 16][wcol]));
                wh[2*jp][0] = tmp[0]; wh[2*jp][1] = tmp[1];
                wh[2*jp+1][0] = tmp[2]; wh[2*jp+1][1] = tmp[3];
            }
            #pragma unroll
            for (int t = 0; t < 2; t++)
                #pragma unroll
                for (int j = 0; j < NT8; j++) mma_bf16(acc[t][j], ah[t], wh[j]);

            ldm_x4(al[0], smem_u32(&sAl[arow     ][acol]));
            ldm_x4(al[1], smem_u32(&sAl[arow + 16][acol]));
            #pragma unroll
            for (int t = 0; t < 2; t++)
                #pragma unroll
                for (int j = 0; j < NT8; j++) mma_bf16(acc[t][j], al[t], wh[j]);

            #pragma unroll
            for (int jp = 0; jp < NT8 / 2; jp++) {
                uint32_t tmp[4];
                ldm_x4(tmp, smem_u32(&sWl[wrow + jp * 16][wcol]));
                wl[2*jp][0] = tmp[0]; wl[2*jp][1] = tmp[1];
                wl[2*jp+1][0] = tmp[2]; wl[2*jp+1][1] = tmp[3];
            }
            #pragma unroll
            for (int t = 0; t < 2; t++)
                #pragma unroll
                for (int j = 0; j < NT8; j++) mma_bf16(acc[t][j], ah[t], wl[j]);
        }
    }

    // epilogue
    #pragma unroll
    for (int t = 0; t < 2; t++) {
        const int m = mB + wm * 32 + t * 16 + (lane >> 2);
        #pragma unroll
        for (int j = 0; j < NT8; j++) {
            const int n = nB + wn * WN + j * 8 + (lane & 3) * 2;
            float2 v0 = make_float2(acc[t][j][0], acc[t][j][1]);
            float2 v1 = make_float2(acc[t][j][2], acc[t][j][3]);
            if (EPI == 1) {
                float b0 = bias[n], b1 = bias[n + 1];
                v0.x += b0; v0.y += b1; v1.x += b0; v1.y += b1;
            }
            if (EPI == 2) {
                float2 p0 = *(const float2*)&C[(size_t)m * ldc + n];
                float2 p1 = *(const float2*)&C[(size_t)(m + 8) * ldc + n];
                v0.x += p0.x; v0.y += p0.y; v1.x += p1.x; v1.y += p1.y;
            }
            *(float2*)&C[(size_t)m * ldc + n]       = v0;
            *(float2*)&C[(size_t)(m + 8) * ldc + n] = v1;
        }
    }
}

// =====================================================================
// Input layernorm over CIN=7 + patch-GEMM layout scatter
// =====================================================================
__global__ void k_patchnorm(const float* __restrict__ x,
                            const float* __restrict__ gam,
                            const float* __restrict__ bet,
                            float* __restrict__ pn)
{
    int idx = blockIdx.x * blockDim.x + threadIdx.x;
    if (idx >= BB * SEQLEN) return;
    int b = idx / SEQLEN, s = idx % SEQLEN;
    const float* xp = x + idx * CINC;
    float sum = 0.f;
    #pragma unroll
    for (int c = 0; c < CINC; c++) sum += xp[c];
    float m = sum * (1.f / CINC);
    float var = 0.f;
    #pragma unroll
    for (int c = 0; c < CINC; c++) { float d = xp[c] - m; var = fmaf(d, d, var); }
    var *= (1.f / CINC);
    float inv = rsqrtf(var + 1e-5f);
    int n = s / PLEN, p = s % PLEN;
    float* o = pn + (b * NPATCH + n) * KPATCH;
    #pragma unroll
    for (int c = 0; c < CINC; c++)
        o[c * PLEN + p] = (xp[c] - m) * inv * gam[c] + bet[c];
}

// =====================================================================
// Row layernorm, width 512
// =====================================================================
__global__ void __launch_bounds__(128)
k_ln(const float* __restrict__ in, float* __restrict__ out,
     const float* __restrict__ gam, const float* __restrict__ bet)
{
    const int row = blockIdx.x;
    const float* x = in + row * DMOD;
    float s = 0.f, ss = 0.f;
    #pragma unroll
    for (int i = threadIdx.x; i < DMOD; i += 128) {
        float v = x[i]; s += v; ss = fmaf(v, v, ss);
    }
    __shared__ float sh1[4], sh2[4];
    #pragma unroll
    for (int o = 16; o > 0; o >>= 1) {
        s  += __shfl_down_sync(0xffffffffu, s,  o);
        ss += __shfl_down_sync(0xffffffffu, ss, o);
    }
    if ((threadIdx.x & 31) == 0) { sh1[threadIdx.x >> 5] = s; sh2[threadIdx.x >> 5] = ss; }
    __syncthreads();
    __shared__ float smean, sinv;
    if (threadIdx.x == 0) {
        float ts  = sh1[0] + sh1[1] + sh1[2] + sh1[3];
        float tss = sh2[0] + sh2[1] + sh2[2] + sh2[3];
        float m   = ts * (1.f / DMOD);
        float var = tss * (1.f / DMOD) - m * m;
        smean = m; sinv = rsqrtf(var + 1e-5f);
    }
    __syncthreads();
    float m = smean, inv = sinv;
    float* o = out + row * DMOD;
    #pragma unroll
    for (int i = threadIdx.x; i < DMOD; i += 128)
        o[i] = (x[i] - m) * inv * gam[i] + bet[i];
}

// =====================================================================
// Depthwise causal conv (DC=4) + silu
// =====================================================================
__global__ void k_conv(const float* __restrict__ xz,
                       const float* __restrict__ cw,
                       const float* __restrict__ cb,
                       float* __restrict__ xc)
{
    int idx = blockIdx.x * blockDim.x + threadIdx.x;
    if (idx >= MROWS * DINNER) return;
    int d  = idx % DINNER;
    int bl = idx / DINNER;
    int l  = bl % NPATCH;
    int b  = bl / NPATCH;
    const float4 w = *(const float4*)(cw + d * 4);
    float acc = cb[d];
    int base = (b * NPATCH) * 2 * DINNER + d;
    if (l >= 3) acc = fmaf(xz[base + (l - 3) * 2 * DINNER], w.x, acc);
    if (l >= 2) acc = fmaf(xz[base + (l - 2) * 2 * DINNER], w.y, acc);
    if (l >= 1) acc = fmaf(xz[base + (l - 1) * 2 * DINNER], w.z, acc);
    acc = fmaf(xz[base + l * 2 * DINNER], w.w, acc);
    xc[idx] = acc / (1.f + __expf(-acc));
}

// =====================================================================
// Selective scan + gating. 4 lanes per (b,d): 4 states each,
// shfl-reduce for y. Structured-A fast path is per-lane (its 4 states).
// grid = (DINNER/32, BB), block = 128 (32 d-slots x 4 lanes)
// =====================================================================
__global__ void __launch_bounds__(128)
k_scan(const float* __restrict__ pre, const float* __restrict__ xc,
       const float* __restrict__ xz,  const float* __restrict__ dbl,
       const float* __restrict__ A_log, const float* __restrict__ Dskip,
       float* __restrict__ y)
{
    const int tid = threadIdx.x;
    const int ng  = tid & 3;                 // state group 0..3
    const int d   = blockIdx.x * 32 + (tid >> 2);
    const int b   = blockIdx.y;

    float a[4];
    bool structured = true;
    #pragma unroll
    for (int i = 0; i < 4; i++) {
        int n = ng * 4 + i;
        a[i] = -__expf(A_log[d * NST + n]);
        structured = structured && (fabsf(a[i] + (float)(n + 1)) <= 1e-4f * (float)(n + 1));
    }
    const float Dv = Dskip[d];
    float h[4] = {0.f, 0.f, 0.f, 0.f};

    __shared__ float sBC[16][32];

    for (int tt = 0; tt < NPATCH; tt += 16) {
        __syncthreads();
        {
            int r = tid >> 3, c = tid & 7;
            float4 v = *(const float4*)&dbl[(b * NPATCH + tt + r) * 64 + 32 + c * 4];
            *(float4*)&sBC[r][c * 4] = v;
        }
        __syncthreads();

        #pragma unroll 4
        for (int t2 = 0; t2 < 16; t2++) {
            int base = b * NPATCH + tt + t2;
            float xv  = pre[base * DINNER + d];
            float xcv = xc [base * DINNER + d];
            float zv  = xz [base * 2 * DINNER + DINNER + d];

            // q = exp(-softplus(xv)) = sigmoid(-xv); delta = softplus(xv)
            float q, delta;
            if (xv > 0.f) {
                float e = __expf(-xv);
                q = e / (1.f + e);
                delta = xv + __logf(1.f + e);
            } else {
                float e = __expf(xv);
                q = 1.f / (1.f + e);
                delta = __logf(1.f + e);
            }

            float pw[4];
            if (structured) {
                // exponents 4ng+1 .. 4ng+4
                float q2 = q * q, q4 = q2 * q2;
                float b1 = (ng & 1) ? q4 : 1.f;
                float b2 = (ng & 2) ? q4 * q4 : 1.f;
                float bs = b1 * b2;                // q^(4ng)
                pw[0] = bs * q;  pw[1] = bs * q2;
                pw[2] = bs * q2 * q; pw[3] = bs * q4;
            } else {
                #pragma unroll
                for (int i = 0; i < 4; i++) pw[i] = __expf(delta * a[i]);
            }

            float dx = delta * xcv;
            float acc = 0.f;
            #pragma unroll
            for (int i = 0; i < 4; i++) {
                int n = ng * 4 + i;
                h[i] = fmaf(pw[i], h[i], dx * sBC[t2][n]);
                acc  = fmaf(h[i], sBC[t2][16 + n], acc);
            }
            acc += __shfl_xor_sync(0xffffffffu, acc, 1);
            acc += __shfl_xor_sync(0xffffffffu, acc, 2);
            if (ng == 0) {
                float sz = zv / (1.f + __expf(-zv));
                y[base * DINNER + d] = (acc + xcv * Dv) * sz;
            }
        }
    }
}

// =====================================================================
// Head GEMM1 split-K (deterministic)
// =====================================================================
__global__ void __launch_bounds__(128)
k_head1(const float* __restrict__ hin, const float* __restrict__ W,
        float* __restrict__ part)
{
    const int j0 = blockIdx.x * 16;
    const int k0 = blockIdx.y * (KFLAT / KSPLIT);
    const int tid = threadIdx.x;
    const int bb = tid / 16, jj = tid % 16;
    __shared__ float shh[BB][129];
    __shared__ float shw[16][129];
    float acc = 0.f;
    for (int kc = 0; kc < KFLAT / KSPLIT; kc += 128) {
        int k = k0 + kc + tid;
        #pragma unroll
        for (int i = 0; i < BB; i++)  shh[i][tid] = hin[i * KFLAT + k];
        #pragma unroll
        for (int i = 0; i < 16; i++)  shw[i][tid] = W[(j0 + i) * KFLAT + k];
        __syncthreads();
        #pragma unroll 8
        for (int k2 = 0; k2 < 128; k2++)
            acc = fmaf(shh[bb][k2], shw[jj][k2], acc);
        __syncthreads();
    }
    part[blockIdx.y * (BB * 128) + bb * 128 + j0 + jj] = acc;
}

__global__ void __launch_bounds__(128)
k_head2(const float* __restrict__ part, const float* __restrict__ hb1,
        const float* __restrict__ hW2,  const float* __restrict__ hb2,
        float* __restrict__ out)
{
    const int b = blockIdx.x;
    const int tid = threadIdx.x;
    __shared__ float g[128];
    float v = 0.f;
    #pragma unroll
    for (int ks = 0; ks < KSPLIT; ks++)
        v += part[ks * (BB * 128) + b * 128 + tid];
    v += hb1[tid];
    g[tid] = 0.5f * v * (1.f + erff(v * 0.70710678118654752f));
    __syncthreads();
    if (tid < HPRED) {
        float acc = hb2[tid];
        #pragma unroll 16
        for (int j = 0; j < 128; j++)
            acc = fmaf(g[j], hW2[tid * 128 + j], acc);
        out[b * HPRED + tid] = acc;
    }
}

// =====================================================================
// Launch
// =====================================================================
static float* symaddr(const void* sym)
{
    void* p = nullptr;
    cudaGetSymbolAddress(&p, sym);
    return (float*)p;
}

extern "C" void kernel_launch(void* const* d_in, const int* in_sizes, int n_in,
                              void* d_out, int out_size)
{
    const float* x      = (const float*)d_in[0];
    const float* in_g   = (const float*)d_in[1];
    const float* in_b   = (const float*)d_in[2];
    const float* pe_W   = (const float*)d_in[3];
    const float* pe_b   = (const float*)d_in[4];
    const float* ln_g   = (const float*)d_in[5];
    const float* ln_b   = (const float*)d_in[6];
    const float* W_in   = (const float*)d_in[7];
    const float* conv_W = (const float*)d_in[8];
    const float* conv_b = (const float*)d_in[9];
    const float* W_x    = (const float*)d_in[10];
    const float* W_dt   = (const float*)d_in[11];
    const float* b_dt   = (const float*)d_in[12];
    const float* A_log  = (const float*)d_in[13];
    const float* Dskip  = (const float*)d_in[14];
    const float* W_out  = (const float*)d_in[15];
    const float* fn_g   = (const float*)d_in[16];
    const float* fn_b   = (const float*)d_in[17];
    const float* hW1    = (const float*)d_in[18];
    const float* hb1    = (const float*)d_in[19];
    const float* hW2    = (const float*)d_in[20];
    const float* hb2    = (const float*)d_in[21];

    float* ph   = symaddr(g_h);
    float* pln  = symaddr(g_ln);
    float* ppn  = symaddr(g_pn);
    float* pxz  = symaddr(g_xz);
    float* pxc  = symaddr(g_xc);
    float* pdbl = symaddr(g_dbl);
    float* ppre = symaddr(g_pre);
    float* py   = symaddr(g_y);
    float* ppart= symaddr(g_part);

    // 1) input LN + patch layout
    k_patchnorm<<<(BB * SEQLEN + 255) / 256, 256>>>(x, in_g, in_b, ppn);

    // 2) patch embedding: h = pn @ pe_W^T + pe_b  (2048 x 512, K=112)
    mgemm<128,1><<<dim3(DMOD / 128, MROWS / 128), 256>>>(
        MROWS, DMOD, KPATCH, ppn, KPATCH, pe_W, KPATCH, pe_b, ph, DMOD);

    // 3) Mamba layers
    for (int i = 0; i < NLAY; i++) {
        k_ln<<<MROWS, 128>>>(ph, pln, ln_g + i * DMOD, ln_b + i * DMOD);

        // xz = ln @ W_in^T  (2048 x 2048, K=512)
        mgemm<128,0><<<dim3(2 * DINNER / 128, MROWS / 128), 256>>>(
            MROWS, 2 * DINNER, DMOD, pln, DMOD,
            W_in + (size_t)i * 2 * DINNER * DMOD, DMOD, nullptr, pxz, 2 * DINNER);

        // depthwise causal conv + silu
        k_conv<<<(MROWS * DINNER + 255) / 256, 256>>>(
            pxz, conv_W + (size_t)i * DINNER * DCONV, conv_b + (size_t)i * DINNER, pxc);

        // dbl = xc @ W_x^T  (2048 x 64, K=1024)
        mgemm<64,0><<<dim3(1, MROWS / 128), 256>>>(
            MROWS, 64, DINNER, pxc, DINNER,
            W_x + (size_t)i * 64 * DINNER, DINNER, nullptr, pdbl, 64);

        // pre = dt @ W_dt^T + b_dt  (2048 x 1024, K=32; A rows stride 64)
        mgemm<128,1><<<dim3(DINNER / 128, MROWS / 128), 256>>>(
            MROWS, DINNER, DTRANK, pdbl, 64,
            W_dt + (size_t)i * DINNER * DTRANK, DTRANK, b_dt + (size_t)i * DINNER,
            ppre, DINNER);

        // fused selective scan + gating
        k_scan<<<dim3(DINNER / 32, BB), 128>>>(
            ppre, pxc, pxz, pdbl,
            A_log + (size_t)i * DINNER * NST, Dskip + (size_t)i * DINNER, py);

        // h += y @ W_out^T  (2048 x 512, K=1024)
        mgemm<128,2><<<dim3(DMOD / 128, MROWS / 128), 256>>>(
            MROWS, DMOD, DINNER, py, DINNER,
            W_out + (size_t)i * DMOD * DINNER, DINNER, nullptr, ph, DMOD);
    }

    // 4) final LN
    k_ln<<<MROWS, 128>>>(ph, pln, fn_g, fn_b);

    // 5) head
    k_head1<<<dim3(8, KSPLIT), 128>>>(pln, hW1, ppart);
    k_head2<<<BB, 128>>>(ppart, hb1, hW2, hb2, (float*)d_out);
}

// round 4
// speedup vs baseline: 1.7798x; 1.2010x over previous
#include <cuda_runtime.h>
#include <cuda_bf16.h>
#include <math.h>
#include <stdint.h>

// ---------------- Problem constants ----------------
#define BB      8
#define SEQLEN  4096
#define CINC    7
#define DMOD    512
#define NLAY    4
#define PLEN    16
#define NPATCH  256
#define NST     16
#define DCONV   4
#define DINNER  1024
#define DTRANK  32
#define MROWS   (BB*NPATCH)    // 2048
#define KPATCH  112
#define KPPAD   128
#define HPRED   96
#define HKS     128            // head split-K blocks
#define KFLAT   (NPATCH*DMOD)  // 131072
#define DBLKS   4              // dbl gemm split-K

// ---------------- fp32 scratch ----------------
__device__ float g_h   [MROWS*DMOD];
__device__ float g_ln  [MROWS*DMOD];          // final LN (head input)
__device__ float g_xz  [MROWS*2*DINNER];
__device__ float g_dbl [MROWS*64];
__device__ float g_pre [MROWS*DINNER];
__device__ float g_dblp[DBLKS*MROWS*64];
__device__ float g_part[HKS*BB*128];

// ---------------- bf16 hi/lo activation planes ----------------
__device__ __nv_bfloat16 g_pnh[MROWS*KPPAD],  g_pnl[MROWS*KPPAD];
__device__ __nv_bfloat16 g_lnh[MROWS*DMOD],   g_lnl[MROWS*DMOD];
__device__ __nv_bfloat16 g_xch[MROWS*DINNER], g_xcl[MROWS*DINNER];
__device__ __nv_bfloat16 g_dth[MROWS*DTRANK], g_dtl[MROWS*DTRANK];
__device__ __nv_bfloat16 g_yh [MROWS*DINNER], g_yl [MROWS*DINNER];

// ---------------- bf16 hi/lo weight planes ----------------
__device__ __nv_bfloat16 g_peWh[DMOD*KPPAD],           g_peWl[DMOD*KPPAD];
__device__ __nv_bfloat16 g_Winh[NLAY*2*DINNER*DMOD],   g_Winl[NLAY*2*DINNER*DMOD];
__device__ __nv_bfloat16 g_Wxh [NLAY*64*DINNER],       g_Wxl [NLAY*64*DINNER];
__device__ __nv_bfloat16 g_Wdth[NLAY*DINNER*DTRANK],   g_Wdtl[NLAY*DINNER*DTRANK];
__device__ __nv_bfloat16 g_Wouth[NLAY*DMOD*DINNER],    g_Woutl[NLAY*DMOD*DINNER];

// =====================================================================
// Helpers
// =====================================================================
static __device__ __forceinline__ uint32_t smem_u32(const void* p) {
    uint32_t a;
    asm("{ .reg .u64 t; cvta.to.shared.u64 t, %1; cvt.u32.u64 %0, t; }"
        : "=r"(a) : "l"(p));
    return a;
}
static __device__ __forceinline__ void ldm_x4(uint32_t* r, uint32_t addr) {
    asm volatile("ldmatrix.sync.aligned.m8n8.x4.shared.b16 {%0,%1,%2,%3}, [%4];"
        : "=r"(r[0]), "=r"(r[1]), "=r"(r[2]), "=r"(r[3]) : "r"(addr));
}
static __device__ __forceinline__ void mma_bf16(float* c, const uint32_t* a,
                                                const uint32_t* b) {
    asm volatile(
        "mma.sync.aligned.m16n8k16.row.col.f32.bf16.bf16.f32 "
        "{%0,%1,%2,%3}, {%4,%5,%6,%7}, {%8,%9}, {%0,%1,%2,%3};"
        : "+f"(c[0]), "+f"(c[1]), "+f"(c[2]), "+f"(c[3])
        : "r"(a[0]), "r"(a[1]), "r"(a[2]), "r"(a[3]), "r"(b[0]), "r"(b[1]));
}
static __device__ __forceinline__ void cp16(uint32_t dst, const void* src) {
    asm volatile("cp.async.cg.shared.global [%0], [%1], 16;"
                 :: "r"(dst), "l"(src));
}
static __device__ __forceinline__ void cp_commit() {
    asm volatile("cp.async.commit_group;");
}
template<int NW> static __device__ __forceinline__ void cp_wait() {
    asm volatile("cp.async.wait_group %0;" :: "n"(NW));
}
static __device__ __forceinline__ void split1(float v, __nv_bfloat16& h, __nv_bfloat16& l) {
    h = __float2bfloat16(v);
    l = __float2bfloat16(v - __bfloat162float(h));
}

// =====================================================================
// Per-launch weight split: fp32 -> bf16 hi/lo planes (grid-stride)
// =====================================================================
__global__ void k_split(const float* __restrict__ src,
                        __nv_bfloat16* __restrict__ h, __nv_bfloat16* __restrict__ l,
                        int rows, int cols, int sld, int dld)
{
    int n = rows * cols;
    for (int i = blockIdx.x * blockDim.x + threadIdx.x; i < n;
         i += gridDim.x * blockDim.x) {
        int r = i / cols, c = i - r * cols;
        float v = src[(size_t)r * sld + c];
        __nv_bfloat16 hh, ll; split1(v, hh, ll);
        h[(size_t)r * dld + c] = hh;
        l[(size_t)r * dld + c] = ll;
    }
}

// =====================================================================
// bf16x3 mma.sync GEMM, cp.async pipelined, pre-split bf16 inputs.
// C[M,N](fp32) = (Ah+Al)[M,K] * (Wh+Wl)[N,K]^T (3 passes, AlWl dropped)
// BM in {64,128}; 8 warps; warp tile 32 x BN/WNW. Ks = K per z-slice.
// EPI: 0=store, 1=store+bias[n], 2=accumulate into C
// =====================================================================
template<int BM, int BN, int EPI>
__global__ void __launch_bounds__(256, 2)
bgemm(int M, int N, int Ks,
      const __nv_bfloat16* __restrict__ Ah, const __nv_bfloat16* __restrict__ Al, int lda,
      const __nv_bfloat16* __restrict__ Wh, const __nv_bfloat16* __restrict__ Wl, int ldw,
      const float* __restrict__ bias, float* __restrict__ C, int ldc, int sliceC)
{
    constexpr int LDS = 40;                 // halves per SMEM row (32 + 8 pad)
    constexpr int WNW = (BM == 128) ? 2 : 4;
    constexpr int WN  = BN / WNW;
    constexpr int NT8 = WN / 8;
    constexpr int APL = BM * LDS, WPL = BN * LDS;   // halves
    constexpr int STG = 2 * APL + 2 * WPL;          // halves per stage

    extern __shared__ __nv_bfloat16 sm[];
    const uint32_t smu = smem_u32(sm);

    const int tid = threadIdx.x, lane = tid & 31, warp = tid >> 5;
    const int wn = warp % WNW, wm = warp / WNW;
    const int mB = blockIdx.y * BM, nB = blockIdx.x * BN;
    const int kbase = blockIdx.z * Ks;
    float* pC = C + (size_t)blockIdx.z * sliceC;

    float acc[2][NT8][4];
    #pragma unroll
    for (int t = 0; t < 2; t++)
        #pragma unroll
        for (int j = 0; j < NT8; j++)
            #pragma unroll
            for (int r = 0; r < 4; r++) acc[t][j][r] = 0.f;

    const int nCh = Ks / 32;

    // ---- stage loader ----
    auto load_stage = [&](int s) {
        const uint32_t sb = smu + (uint32_t)((s & 1) * STG) * 2;
        const int k0 = kbase + s * 32;
        #pragma unroll
        for (int i = tid; i < BM * 4; i += 256) {
            int row = i >> 2, c = i & 3;
            size_t g = (size_t)(mB + row) * lda + k0 + c * 8;
            uint32_t d = sb + (uint32_t)(row * LDS + c * 8) * 2;
            cp16(d, Ah + g);
            cp16(d + APL * 2, Al + g);
        }
        #pragma unroll
        for (int i = tid; i < BN * 4; i += 256) {
            int row = i >> 2, c = i & 3;
            size_t g = (size_t)(nB + row) * ldw + k0 + c * 8;
            uint32_t d = sb + (uint32_t)(2 * APL + row * LDS + c * 8) * 2;
            cp16(d, Wh + g);
            cp16(d + WPL * 2, Wl + g);
        }
        cp_commit();
    };

    load_stage(0);

    for (int s = 0; s < nCh; s++) {
        if (s + 1 < nCh) { load_stage(s + 1); cp_wait<1>(); }
        else             { cp_wait<0>(); }
        __syncthreads();

        const uint32_t sb = smu + (uint32_t)((s & 1) * STG) * 2;
        #pragma unroll
        for (int k16 = 0; k16 < 2; k16++) {
            uint32_t ah[2][4], al[2][4], wf[NT8][2];
            const int arow = wm * 32 + (lane & 15);
            const int acol = k16 * 16 + (lane >> 4) * 8;
            const uint32_t aAddr = sb + (uint32_t)(arow * LDS + acol) * 2;
            ldm_x4(ah[0], aAddr);
            ldm_x4(ah[1], aAddr + 16 * LDS * 2);

            const int wrow = wn * WN + ((lane >> 4) << 3) + (lane & 7);
            const int wcol = k16 * 16 + ((lane >> 3) & 1) * 8;
            const uint32_t wAddr = sb + (uint32_t)(2 * APL + wrow * LDS + wcol) * 2;
            #pragma unroll
            for (int jp = 0; jp < NT8 / 2; jp++) {
                uint32_t t4[4];
                ldm_x4(t4, wAddr + jp * 16 * LDS * 2);
                wf[2*jp][0] = t4[0]; wf[2*jp][1] = t4[1];
                wf[2*jp+1][0] = t4[2]; wf[2*jp+1][1] = t4[3];
            }
            #pragma unroll
            for (int t = 0; t < 2; t++)
                #pragma unroll
                for (int j = 0; j < NT8; j++) mma_bf16(acc[t][j], ah[t], wf[j]);

            ldm_x4(al[0], aAddr + APL * 2);
            ldm_x4(al[1], aAddr + APL * 2 + 16 * LDS * 2);
            #pragma unroll
            for (int t = 0; t < 2; t++)
                #pragma unroll
                for (int j = 0; j < NT8; j++) mma_bf16(acc[t][j], al[t], wf[j]);

            #pragma unroll
            for (int jp = 0; jp < NT8 / 2; jp++) {
                uint32_t t4[4];
                ldm_x4(t4, wAddr + WPL * 2 + jp * 16 * LDS * 2);
                wf[2*jp][0] = t4[0]; wf[2*jp][1] = t4[1];
                wf[2*jp+1][0] = t4[2]; wf[2*jp+1][1] = t4[3];
            }
            #pragma unroll
            for (int t = 0; t < 2; t++)
                #pragma unroll
                for (int j = 0; j < NT8; j++) mma_bf16(acc[t][j], ah[t], wf[j]);
        }
        __syncthreads();
    }

    // ---- epilogue ----
    #pragma unroll
    for (int t = 0; t < 2; t++) {
        const int m = mB + wm * 32 + t * 16 + (lane >> 2);
        #pragma unroll
        for (int j = 0; j < NT8; j++) {
            const int n = nB + wn * WN + j * 8 + (lane & 3) * 2;
            float2 v0 = make_float2(acc[t][j][0], acc[t][j][1]);
            float2 v1 = make_float2(acc[t][j][2], acc[t][j][3]);
            if (EPI == 1) {
                float b0 = bias[n], b1 = bias[n + 1];
                v0.x += b0; v0.y += b1; v1.x += b0; v1.y += b1;
            }
            if (EPI == 2) {
                float2 p0 = *(const float2*)&pC[(size_t)m * ldc + n];
                float2 p1 = *(const float2*)&pC[(size_t)(m + 8) * ldc + n];
                v0.x += p0.x; v0.y += p0.y; v1.x += p1.x; v1.y += p1.y;
            }
            *(float2*)&pC[(size_t)m * ldc + n]       = v0;
            *(float2*)&pC[(size_t)(m + 8) * ldc + n] = v1;
        }
    }
}

// =====================================================================
// Input layernorm (CIN=7) + patch layout, writes bf16 hi/lo planes
// =====================================================================
__global__ void k_patchnorm(const float* __restrict__ x,
                            const float* __restrict__ gam,
                            const float* __restrict__ bet)
{
    int idx = blockIdx.x * blockDim.x + threadIdx.x;
    if (idx >= BB * SEQLEN) return;
    int b = idx / SEQLEN, s = idx % SEQLEN;
    const float* xp = x + idx * CINC;
    float sum = 0.f;
    #pragma unroll
    for (int c = 0; c < CINC; c++) sum += xp[c];
    float m = sum * (1.f / CINC);
    float var = 0.f;
    #pragma unroll
    for (int c = 0; c < CINC; c++) { float d = xp[c] - m; var = fmaf(d, d, var); }
    var *= (1.f / CINC);
    float inv = rsqrtf(var + 1e-5f);
    int n = s / PLEN, p = s % PLEN;
    size_t ro = (size_t)(b * NPATCH + n) * KPPAD;
    #pragma unroll
    for (int c = 0; c < CINC; c++) {
        float v = (xp[c] - m) * inv * gam[c] + bet[c];
        __nv_bfloat16 h, l; split1(v, h, l);
        g_pnh[ro + c * PLEN + p] = h;
        g_pnl[ro + c * PLEN + p] = l;
    }
}

// =====================================================================
// Row layernorm width 512. SPLIT=1: bf16 planes; SPLIT=0: fp32 out.
// =====================================================================
template<int SPLIT>
__global__ void __launch_bounds__(128)
k_ln(const float* __restrict__ in, float* __restrict__ outf,
     __nv_bfloat16* __restrict__ oh, __nv_bfloat16* __restrict__ ol,
     const float* __restrict__ gam, const float* __restrict__ bet)
{
    const int row = blockIdx.x;
    const float* x = in + (size_t)row * DMOD;
    float s = 0.f, ss = 0.f;
    #pragma unroll
    for (int i = threadIdx.x; i < DMOD; i += 128) {
        float v = x[i]; s += v; ss = fmaf(v, v, ss);
    }
    __shared__ float sh1[4], sh2[4];
    #pragma unroll
    for (int o = 16; o > 0; o >>= 1) {
        s  += __shfl_down_sync(0xffffffffu, s,  o);
        ss += __shfl_down_sync(0xffffffffu, ss, o);
    }
    if ((threadIdx.x & 31) == 0) { sh1[threadIdx.x >> 5] = s; sh2[threadIdx.x >> 5] = ss; }
    __syncthreads();
    __shared__ float smean, sinv;
    if (threadIdx.x == 0) {
        float ts  = sh1[0] + sh1[1] + sh1[2] + sh1[3];
        float tss = sh2[0] + sh2[1] + sh2[2] + sh2[3];
        float m   = ts * (1.f / DMOD);
        float var = tss * (1.f / DMOD) - m * m;
        smean = m; sinv = rsqrtf(var + 1e-5f);
    }
    __syncthreads();
    float m = smean, inv = sinv;
    #pragma unroll
    for (int i = threadIdx.x; i < DMOD; i += 128) {
        float v = (x[i] - m) * inv * gam[i] + bet[i];
        if (SPLIT) {
            __nv_bfloat16 h, l; split1(v, h, l);
            oh[(size_t)row * DMOD + i] = h;
            ol[(size_t)row * DMOD + i] = l;
        } else {
            outf[(size_t)row * DMOD + i] = v;
        }
    }
}

// =====================================================================
// Depthwise causal conv (DC=4) + silu -> bf16 hi/lo planes
// =====================================================================
__global__ void k_conv(const float* __restrict__ xz,
                       const float* __restrict__ cw,
                       const float* __restrict__ cb)
{
    int idx = blockIdx.x * blockDim.x + threadIdx.x;
    if (idx >= MROWS * DINNER) return;
    int d  = idx % DINNER;
    int bl = idx / DINNER;
    int l  = bl % NPATCH;
    int b  = bl / NPATCH;
    const float4 w = *(const float4*)(cw + d * 4);
    float acc = cb[d];
    size_t base = (size_t)(b * NPATCH) * 2 * DINNER + d;
    if (l >= 3) acc = fmaf(xz[base + (size_t)(l - 3) * 2 * DINNER], w.x, acc);
    if (l >= 2) acc = fmaf(xz[base + (size_t)(l - 2) * 2 * DINNER], w.y, acc);
    if (l >= 1) acc = fmaf(xz[base + (size_t)(l - 1) * 2 * DINNER], w.z, acc);
    acc = fmaf(xz[base + (size_t)l * 2 * DINNER], w.w, acc);
    float v = acc / (1.f + __expf(-acc));
    __nv_bfloat16 h, lo; split1(v, h, lo);
    g_xch[idx] = h; g_xcl[idx] = lo;
}

// =====================================================================
// dbl split-K reduce: 4 partials -> fp32 dbl + dt hi/lo planes
// =====================================================================
__global__ void k_dblred(const float* __restrict__ part)
{
    int idx = blockIdx.x * blockDim.x + threadIdx.x;
    if (idx >= MROWS * 64) return;
    float v = part[idx] + part[idx + MROWS * 64]
            + part[idx + 2 * MROWS * 64] + part[idx + 3 * MROWS * 64];
    g_dbl[idx] = v;
    int col = idx & 63, row = idx >> 6;
    if (col < DTRANK) {
        __nv_bfloat16 h, l; split1(v, h, l);
        g_dth[row * DTRANK + col] = h;
        g_dtl[row * DTRANK + col] = l;
    }
}

// =====================================================================
// Selective scan + gating. 4 lanes per (b,d). Writes y hi/lo planes.
// =====================================================================
__global__ void __launch_bounds__(128)
k_scan(const float* __restrict__ pre, const float* __restrict__ xz,
       const float* __restrict__ dbl,
       const float* __restrict__ A_log, const float* __restrict__ Dskip)
{
    const int tid = threadIdx.x;
    const int ng  = tid & 3;
    const int d   = blockIdx.x * 32 + (tid >> 2);
    const int b   = blockIdx.y;

    float a[4];
    bool structured = true;
    #pragma unroll
    for (int i = 0; i < 4; i++) {
        int n = ng * 4 + i;
        a[i] = -__expf(A_log[d * NST + n]);
        structured = structured && (fabsf(a[i] + (float)(n + 1)) <= 1e-4f * (float)(n + 1));
    }
    const float Dv = Dskip[d];
    float h[4] = {0.f, 0.f, 0.f, 0.f};

    __shared__ float sBC[16][32];

    for (int tt = 0; tt < NPATCH; tt += 16) {
        __syncthreads();
        {
            int r = tid >> 3, c = tid & 7;
            float4 v = *(const float4*)&dbl[(b * NPATCH + tt + r) * 64 + 32 + c * 4];
            *(float4*)&sBC[r][c * 4] = v;
        }
        __syncthreads();

        #pragma unroll 4
        for (int t2 = 0; t2 < 16; t2++) {
            int base = b * NPATCH + tt + t2;
            size_t di = (size_t)base * DINNER + d;
            float xv  = pre[di];
            float xcv = __bfloat162float(g_xch[di]) + __bfloat162float(g_xcl[di]);
            float zv  = xz[(size_t)base * 2 * DINNER + DINNER + d];

            float q, delta;
            if (xv > 0.f) {
                float e = __expf(-xv);
                q = e / (1.f + e);
                delta = xv + __logf(1.f + e);
            } else {
                float e = __expf(xv);
                q = 1.f / (1.f + e);
                delta = __logf(1.f + e);
            }

            float pw[4];
            if (structured) {
                float q2 = q * q, q4 = q2 * q2;
                float b1 = (ng & 1) ? q4 : 1.f;
                float b2 = (ng & 2) ? q4 * q4 : 1.f;
                float bs = b1 * b2;
                pw[0] = bs * q;      pw[1] = bs * q2;
                pw[2] = bs * q2 * q; pw[3] = bs * q4;
            } else {
                #pragma unroll
                for (int i = 0; i < 4; i++) pw[i] = __expf(delta * a[i]);
            }

            float dx = delta * xcv;
            float acc = 0.f;
            #pragma unroll
            for (int i = 0; i < 4; i++) {
                int n = ng * 4 + i;
                h[i] = fmaf(pw[i], h[i], dx * sBC[t2][n]);
                acc  = fmaf(h[i], sBC[t2][16 + n], acc);
            }
            acc += __shfl_xor_sync(0xffffffffu, acc, 1);
            acc += __shfl_xor_sync(0xffffffffu, acc, 2);
            if (ng == 0) {
                float sz = zv / (1.f + __expf(-zv));
                float yv = (acc + xcv * Dv) * sz;
                __nv_bfloat16 hh, ll; split1(yv, hh, ll);
                g_yh[di] = hh; g_yl[di] = ll;
            }
        }
    }
}

// =====================================================================
// Head GEMM1: split-K 128 blocks, thread-per-column, 8 reg accumulators
// =====================================================================
__global__ void __launch_bounds__(128)
k_head1(const float* __restrict__ hin, const float* __restrict__ W,
        float* __restrict__ part)
{
    const int z = blockIdx.x;                  // 0..HKS-1
    const int kbase = z * (KFLAT / HKS);       // 1024-wide chunk
    const int tid = threadIdx.x;               // output column j
    __shared__ float shw[128][33];
    __shared__ float shh[8][33];
    float acc[8] = {0.f,0.f,0.f,0.f,0.f,0.f,0.f,0.f};

    for (int kc = 0; kc < KFLAT / HKS; kc += 32) {
        const int k0 = kbase + kc;
        #pragma unroll
        for (int q = 0; q < 8; q++) {
            float4 v = *(const float4*)&W[(size_t)tid * KFLAT + k0 + q * 4];
            shw[tid][q*4+0] = v.x; shw[tid][q*4+1] = v.y;
            shw[tid][q*4+2] = v.z; shw[tid][q*4+3] = v.w;
        }
        if (tid < 64) {
            int b = tid >> 3, qq = tid & 7;
            float4 v = *(const float4*)&hin[(size_t)b * KFLAT + k0 + qq * 4];
            shh[b][qq*4+0] = v.x; shh[b][qq*4+1] = v.y;
            shh[b][qq*4+2] = v.z; shh[b][qq*4+3] = v.w;
        }
        __syncthreads();
        #pragma unroll 8
        for (int kk = 0; kk < 32; kk++) {
            float w = shw[tid][kk];
            #pragma unroll
            for (int b = 0; b < 8; b++)
                acc[b] = fmaf(w, shh[b][kk], acc[b]);
        }
        __syncthreads();
    }
    #pragma unroll
    for (int b = 0; b < 8; b++)
        part[(size_t)z * (BB * 128) + b * 128 + tid] = acc[b];
}

__global__ void __launch_bounds__(128)
k_head2(const float* __restrict__ part, const float* __restrict__ hb1,
        const float* __restrict__ hW2,  const float* __restrict__ hb2,
        float* __restrict__ out)
{
    const int b = blockIdx.x;
    const int tid = threadIdx.x;
    __shared__ float g[128];
    float v = 0.f;
    for (int z = 0; z < HKS; z++)
        v += part[(size_t)z * (BB * 128) + b * 128 + tid];
    v += hb1[tid];
    g[tid] = 0.5f * v * (1.f + erff(v * 0.70710678118654752f));
    __syncthreads();
    if (tid < HPRED) {
        float acc = hb2[tid];
        #pragma unroll 16
        for (int j = 0; j < 128; j++)
            acc = fmaf(g[j], hW2[tid * 128 + j], acc);
        out[b * HPRED + tid] = acc;
    }
}

// =====================================================================
// Launch
// =====================================================================
static void* symaddr(const void* sym)
{
    void* p = nullptr;
    cudaGetSymbolAddress(&p, sym);
    return p;
}

#define STGB(BM, BN) ((2 * (BM) * 40 + 2 * (BN) * 40) * 2)
#define SMSZ(BM, BN) (2 * STGB(BM, BN))

extern "C" void kernel_launch(void* const* d_in, const int* in_sizes, int n_in,
                              void* d_out, int out_size)
{
    const float* x      = (const float*)d_in[0];
    const float* in_g   = (const float*)d_in[1];
    const float* in_b   = (const float*)d_in[2];
    const float* pe_W   = (const float*)d_in[3];
    const float* pe_b   = (const float*)d_in[4];
    const float* ln_g   = (const float*)d_in[5];
    const float* ln_b   = (const float*)d_in[6];
    const float* W_in   = (const float*)d_in[7];
    const float* conv_W = (const float*)d_in[8];
    const float* conv_b = (const float*)d_in[9];
    const float* W_x    = (const float*)d_in[10];
    const float* W_dt   = (const float*)d_in[11];
    const float* b_dt   = (const float*)d_in[12];
    const float* A_log  = (const float*)d_in[13];
    const float* Dskip  = (const float*)d_in[14];
    const float* W_out  = (const float*)d_in[15];
    const float* fn_g   = (const float*)d_in[16];
    const float* fn_b   = (const float*)d_in[17];
    const float* hW1    = (const float*)d_in[18];
    const float* hb1    = (const float*)d_in[19];
    const float* hW2    = (const float*)d_in[20];
    const float* hb2    = (const float*)d_in[21];

    float* ph    = (float*)symaddr(g_h);
    float* pln   = (float*)symaddr(g_ln);
    float* pxz   = (float*)symaddr(g_xz);
    float* pdbl  = (float*)symaddr(g_dbl);
    float* ppre  = (float*)symaddr(g_pre);
    float* pdblp = (float*)symaddr(g_dblp);
    float* ppart = (float*)symaddr(g_part);

    __nv_bfloat16* pnh = (__nv_bfloat16*)symaddr(g_pnh);
    __nv_bfloat16* pnl = (__nv_bfloat16*)symaddr(g_pnl);
    __nv_bfloat16* lnh = (__nv_bfloat16*)symaddr(g_lnh);
    __nv_bfloat16* lnl = (__nv_bfloat16*)symaddr(g_lnl);
    __nv_bfloat16* xch = (__nv_bfloat16*)symaddr(g_xch);
    __nv_bfloat16* xcl = (__nv_bfloat16*)symaddr(g_xcl);
    __nv_bfloat16* dth = (__nv_bfloat16*)symaddr(g_dth);
    __nv_bfloat16* dtl = (__nv_bfloat16*)symaddr(g_dtl);
    __nv_bfloat16* yh  = (__nv_bfloat16*)symaddr(g_yh);
    __nv_bfloat16* yl  = (__nv_bfloat16*)symaddr(g_yl);

    __nv_bfloat16* peWh = (__nv_bfloat16*)symaddr(g_peWh);
    __nv_bfloat16* peWl = (__nv_bfloat16*)symaddr(g_peWl);
    __nv_bfloat16* Winh = (__nv_bfloat16*)symaddr(g_Winh);
    __nv_bfloat16* Winl = (__nv_bfloat16*)symaddr(g_Winl);
    __nv_bfloat16* Wxh  = (__nv_bfloat16*)symaddr(g_Wxh);
    __nv_bfloat16* Wxl  = (__nv_bfloat16*)symaddr(g_Wxl);
    __nv_bfloat16* Wdth = (__nv_bfloat16*)symaddr(g_Wdth);
    __nv_bfloat16* Wdtl = (__nv_bfloat16*)symaddr(g_Wdtl);
    __nv_bfloat16* Wouth= (__nv_bfloat16*)symaddr(g_Wouth);
    __nv_bfloat16* Woutl= (__nv_bfloat16*)symaddr(g_Woutl);

    static bool attr_done = false;
    if (!attr_done) {
        cudaFuncSetAttribute(bgemm<128,128,0>, cudaFuncAttributeMaxDynamicSharedMemorySize, SMSZ(128,128));
        cudaFuncSetAttribute(bgemm<128,128,1>, cudaFuncAttributeMaxDynamicSharedMemorySize, SMSZ(128,128));
        cudaFuncSetAttribute(bgemm<64,128,1>,  cudaFuncAttributeMaxDynamicSharedMemorySize, SMSZ(64,128));
        cudaFuncSetAttribute(bgemm<64,128,2>,  cudaFuncAttributeMaxDynamicSharedMemorySize, SMSZ(64,128));
        cudaFuncSetAttribute(bgemm<64,64,0>,   cudaFuncAttributeMaxDynamicSharedMemorySize, SMSZ(64,64));
        attr_done = true;
    }

    // 0) weight splits (per-launch prep)
    k_split<<<256, 256>>>(pe_W,  peWh, peWl, DMOD, KPATCH, KPATCH, KPPAD);
    k_split<<<2048, 256>>>(W_in,  Winh, Winl, NLAY*2*DINNER, DMOD, DMOD, DMOD);
    k_split<<<256, 256>>>(W_x,   Wxh,  Wxl,  NLAY*64, DINNER, DINNER, DINNER);
    k_split<<<256, 256>>>(W_dt,  Wdth, Wdtl, NLAY*DINNER, DTRANK, DTRANK, DTRANK);
    k_split<<<1024, 256>>>(W_out, Wouth, Woutl, NLAY*DMOD, DINNER, DINNER, DINNER);

    // 1) input LN + patch planes
    k_patchnorm<<<(BB * SEQLEN + 255) / 256, 256>>>(x, in_g, in_b);

    // 2) patch embed: h = pn @ peW^T + pe_b   (2048x512, K=128 padded)
    bgemm<64,128,1><<<dim3(DMOD/128, MROWS/64), 256, SMSZ(64,128)>>>(
        MROWS, DMOD, KPPAD, pnh, pnl, KPPAD, peWh, peWl, KPPAD, pe_b, ph, DMOD, 0);

    // 3) Mamba layers
    for (int i = 0; i < NLAY; i++) {
        k_ln<1><<<MROWS, 128>>>(ph, nullptr, lnh, lnl,
                                ln_g + i * DMOD, ln_b + i * DMOD);

        // xz = ln @ W_in^T  (2048 x 2048, K=512)
        bgemm<128,128,0><<<dim3(2*DINNER/128, MROWS/128), 256, SMSZ(128,128)>>>(
            MROWS, 2*DINNER, DMOD, lnh, lnl, DMOD,
            Winh + (size_t)i*2*DINNER*DMOD, Winl + (size_t)i*2*DINNER*DMOD, DMOD,
            nullptr, pxz, 2*DINNER, 0);

        k_conv<<<(MROWS * DINNER + 255) / 256, 256>>>(
            pxz, conv_W + (size_t)i*DINNER*DCONV, conv_b + (size_t)i*DINNER);

        // dbl partial = xc @ W_x^T  (2048 x 64, K split 4 x 256)
        bgemm<64,64,0><<<dim3(1, MROWS/64, DBLKS), 256, SMSZ(64,64)>>>(
            MROWS, 64, DINNER/DBLKS, xch, xcl, DINNER,
            Wxh + (size_t)i*64*DINNER, Wxl + (size_t)i*64*DINNER, DINNER,
            nullptr, pdblp, 64, MROWS*64);
        k_dblred<<<(MROWS*64 + 255) / 256, 256>>>(pdblp);

        // pre = dt @ W_dt^T + b_dt  (2048 x 1024, K=32)
        bgemm<128,128,1><<<dim3(DINNER/128, MROWS/128), 256, SMSZ(128,128)>>>(
            MROWS, DINNER, DTRANK, dth, dtl, DTRANK,
            Wdth + (size_t)i*DINNER*DTRANK, Wdtl + (size_t)i*DINNER*DTRANK, DTRANK,
            b_dt + (size_t)i*DINNER, ppre, DINNER, 0);

        k_scan<<<dim3(DINNER/32, BB), 128>>>(
            ppre, pxz, pdbl,
            A_log + (size_t)i*DINNER*NST, Dskip + (size_t)i*DINNER);

        // h += y @ W_out^T  (2048 x 512, K=1024)
        bgemm<64,128,2><<<dim3(DMOD/128, MROWS/64), 256, SMSZ(64,128)>>>(
            MROWS, DMOD, DINNER, yh, yl, DINNER,
            Wouth + (size_t)i*DMOD*DINNER, Woutl + (size_t)i*DMOD*DINNER, DINNER,
            nullptr, ph, DMOD, 0);
    }

    // 4) final LN (fp32 for head)
    k_ln<0><<<MROWS, 128>>>(ph, pln, nullptr, nullptr, fn_g, fn_b);

    // 5) head
    k_head1<<<HKS, 128>>>(pln, hW1, ppart);
    k_head2<<<BB, 128>>>(ppart, hb1, hW2, hb2, (float*)d_out);
}

// round 7
// speedup vs baseline: 1.8713x; 1.0514x over previous
#include <cuda_runtime.h>
#include <cuda_bf16.h>
#include <math.h>
#include <stdint.h>

// ---------------- Problem constants ----------------
#define BB      8
#define SEQLEN  4096
#define CINC    7
#define DMOD    512
#define NLAY    4
#define PLEN    16
#define NPATCH  256
#define NST     16
#define DCONV   4
#define DINNER  1024
#define DTRANK  32
#define MROWS   (BB*NPATCH)    // 2048
#define KPATCH  112
#define KPPAD   128
#define HPRED   96
#define HKS     128
#define KFLAT   (NPATCH*DMOD)  // 131072
#define DBLKS   4

// ---------------- fp32 scratch ----------------
__device__ float g_h   [MROWS*DMOD];
__device__ float g_ln  [MROWS*DMOD];
__device__ float g_xz  [MROWS*2*DINNER];
__device__ float g_dbl [MROWS*64];
__device__ float g_dblp[DBLKS*MROWS*64];
__device__ float g_part[HKS*BB*128];

// ---------------- bf16 hi/lo activation planes ----------------
__device__ __nv_bfloat16 g_pnh[MROWS*KPPAD],  g_pnl[MROWS*KPPAD];
__device__ __nv_bfloat16 g_lnh[MROWS*DMOD],   g_lnl[MROWS*DMOD];
__device__ __nv_bfloat16 g_xch[MROWS*DINNER], g_xcl[MROWS*DINNER];
__device__ __nv_bfloat16 g_yh [MROWS*DINNER], g_yl [MROWS*DINNER];

// ---------------- bf16 hi/lo weight planes ----------------
__device__ __nv_bfloat16 g_peWh[DMOD*KPPAD],         g_peWl[DMOD*KPPAD];
__device__ __nv_bfloat16 g_Winh[NLAY*2*DINNER*DMOD], g_Winl[NLAY*2*DINNER*DMOD];
__device__ __nv_bfloat16 g_Wxh [NLAY*64*DINNER],     g_Wxl [NLAY*64*DINNER];
__device__ __nv_bfloat16 g_Wouth[NLAY*DMOD*DINNER],  g_Woutl[NLAY*DMOD*DINNER];

// =====================================================================
// Helpers
// =====================================================================
static __device__ __forceinline__ uint32_t smem_u32(const void* p) {
    uint32_t a;
    asm("{ .reg .u64 t; cvta.to.shared.u64 t, %1; cvt.u32.u64 %0, t; }"
        : "=r"(a) : "l"(p));
    return a;
}
static __device__ __forceinline__ void ldm_x4(uint32_t* r, uint32_t addr) {
    asm volatile("ldmatrix.sync.aligned.m8n8.x4.shared.b16 {%0,%1,%2,%3}, [%4];"
        : "=r"(r[0]), "=r"(r[1]), "=r"(r[2]), "=r"(r[3]) : "r"(addr));
}
static __device__ __forceinline__ void mma_bf16(float* c, const uint32_t* a,
                                                const uint32_t* b) {
    asm volatile(
        "mma.sync.aligned.m16n8k16.row.col.f32.bf16.bf16.f32 "
        "{%0,%1,%2,%3}, {%4,%5,%6,%7}, {%8,%9}, {%0,%1,%2,%3};"
        : "+f"(c[0]), "+f"(c[1]), "+f"(c[2]), "+f"(c[3])
        : "r"(a[0]), "r"(a[1]), "r"(a[2]), "r"(a[3]), "r"(b[0]), "r"(b[1]));
}
static __device__ __forceinline__ void cp16(uint32_t dst, const void* src) {
    asm volatile("cp.async.cg.shared.global [%0], [%1], 16;"
                 :: "r"(dst), "l"(src));
}
static __device__ __forceinline__ void cp_commit() {
    asm volatile("cp.async.commit_group;");
}
template<int NW> static __device__ __forceinline__ void cp_wait() {
    asm volatile("cp.async.wait_group %0;" :: "n"(NW));
}
static __device__ __forceinline__ void split1(float v, __nv_bfloat16& h, __nv_bfloat16& l) {
    h = __float2bfloat16(v);
    l = __float2bfloat16(v - __bfloat162float(h));
}

// =====================================================================
// Fused weight split: all weights in one launch (grid-stride segments)
// =====================================================================
__global__ void k_splitall(const float* __restrict__ peW,
                           const float* __restrict__ Win,
                           const float* __restrict__ Wx,
                           const float* __restrict__ Wout)
{
    const int t0 = blockIdx.x * blockDim.x + threadIdx.x;
    const int stride = gridDim.x * blockDim.x;
    // peW: 512 x 112 -> padded ld 128
    for (int i = t0; i < DMOD * KPATCH; i += stride) {
        int r = i / KPATCH, c = i - r * KPATCH;
        __nv_bfloat16 h, l; split1(peW[i], h, l);
        g_peWh[r * KPPAD + c] = h; g_peWl[r * KPPAD + c] = l;
    }
    for (int i = t0; i < NLAY * 2 * DINNER * DMOD; i += stride) {
        __nv_bfloat16 h, l; split1(Win[i], h, l);
        g_Winh[i] = h; g_Winl[i] = l;
    }
    for (int i = t0; i < NLAY * 64 * DINNER; i += stride) {
        __nv_bfloat16 h, l; split1(Wx[i], h, l);
        g_Wxh[i] = h; g_Wxl[i] = l;
    }
    for (int i = t0; i < NLAY * DMOD * DINNER; i += stride) {
        __nv_bfloat16 h, l; split1(Wout[i], h, l);
        g_Wouth[i] = h; g_Woutl[i] = l;
    }
}

// =====================================================================
// bf16x3 mma.sync GEMM, cp.async pipelined, pre-split bf16 inputs.
// =====================================================================
template<int BM, int BN, int EPI>
__global__ void __launch_bounds__(256, 2)
bgemm(int M, int N, int Ks,
      const __nv_bfloat16* __restrict__ Ah, const __nv_bfloat16* __restrict__ Al, int lda,
      const __nv_bfloat16* __restrict__ Wh, const __nv_bfloat16* __restrict__ Wl, int ldw,
      const float* __restrict__ bias, float* __restrict__ C, int ldc, int sliceC)
{
    constexpr int LDS = 40;
    constexpr int WNW = (BM == 128) ? 2 : 4;
    constexpr int WN  = BN / WNW;
    constexpr int NT8 = WN / 8;
    constexpr int APL = BM * LDS, WPL = BN * LDS;
    constexpr int STG = 2 * APL + 2 * WPL;

    extern __shared__ __nv_bfloat16 sm[];
    const uint32_t smu = smem_u32(sm);

    const int tid = threadIdx.x, lane = tid & 31, warp = tid >> 5;
    const int wn = warp % WNW, wm = warp / WNW;
    const int mB = blockIdx.y * BM, nB = blockIdx.x * BN;
    const int kbase = blockIdx.z * Ks;
    float* pC = C + (size_t)blockIdx.z * sliceC;

    float acc[2][NT8][4];
    #pragma unroll
    for (int t = 0; t < 2; t++)
        #pragma unroll
        for (int j = 0; j < NT8; j++)
            #pragma unroll
            for (int r = 0; r < 4; r++) acc[t][j][r] = 0.f;

    const int nCh = Ks / 32;

    auto load_stage = [&](int s) {
        const uint32_t sb = smu + (uint32_t)((s & 1) * STG) * 2;
        const int k0 = kbase + s * 32;
        #pragma unroll
        for (int i = tid; i < BM * 4; i += 256) {
            int row = i >> 2, c = i & 3;
            size_t g = (size_t)(mB + row) * lda + k0 + c * 8;
            uint32_t d = sb + (uint32_t)(row * LDS + c * 8) * 2;
            cp16(d, Ah + g);
            cp16(d + APL * 2, Al + g);
        }
        #pragma unroll
        for (int i = tid; i < BN * 4; i += 256) {
            int row = i >> 2, c = i & 3;
            size_t g = (size_t)(nB + row) * ldw + k0 + c * 8;
            uint32_t d = sb + (uint32_t)(2 * APL + row * LDS + c * 8) * 2;
            cp16(d, Wh + g);
            cp16(d + WPL * 2, Wl + g);
        }
        cp_commit();
    };

    load_stage(0);

    for (int s = 0; s < nCh; s++) {
        if (s + 1 < nCh) { load_stage(s + 1); cp_wait<1>(); }
        else             { cp_wait<0>(); }
        __syncthreads();

        const uint32_t sb = smu + (uint32_t)((s & 1) * STG) * 2;
        #pragma unroll
        for (int k16 = 0; k16 < 2; k16++) {
            uint32_t ah[2][4], al[2][4], wf[NT8][2];
            const int arow = wm * 32 + (lane & 15);
            const int acol = k16 * 16 + (lane >> 4) * 8;
            const uint32_t aAddr = sb + (uint32_t)(arow * LDS + acol) * 2;
            ldm_x4(ah[0], aAddr);
            ldm_x4(ah[1], aAddr + 16 * LDS * 2);

            const int wrow = wn * WN + ((lane >> 4) << 3) + (lane & 7);
            const int wcol = k16 * 16 + ((lane >> 3) & 1) * 8;
            const uint32_t wAddr = sb + (uint32_t)(2 * APL + wrow * LDS + wcol) * 2;
            #pragma unroll
            for (int jp = 0; jp < NT8 / 2; jp++) {
                uint32_t t4[4];
                ldm_x4(t4, wAddr + jp * 16 * LDS * 2);
                wf[2*jp][0] = t4[0]; wf[2*jp][1] = t4[1];
                wf[2*jp+1][0] = t4[2]; wf[2*jp+1][1] = t4[3];
            }
            #pragma unroll
            for (int t = 0; t < 2; t++)
                #pragma unroll
                for (int j = 0; j < NT8; j++) mma_bf16(acc[t][j], ah[t], wf[j]);

            ldm_x4(al[0], aAddr + APL * 2);
            ldm_x4(al[1], aAddr + APL * 2 + 16 * LDS * 2);
            #pragma unroll
            for (int t = 0; t < 2; t++)
                #pragma unroll
                for (int j = 0; j < NT8; j++) mma_bf16(acc[t][j], al[t], wf[j]);

            #pragma unroll
            for (int jp = 0; jp < NT8 / 2; jp++) {
                uint32_t t4[4];
                ldm_x4(t4, wAddr + WPL * 2 + jp * 16 * LDS * 2);
                wf[2*jp][0] = t4[0]; wf[2*jp][1] = t4[1];
                wf[2*jp+1][0] = t4[2]; wf[2*jp+1][1] = t4[3];
            }
            #pragma unroll
            for (int t = 0; t < 2; t++)
                #pragma unroll
                for (int j = 0; j < NT8; j++) mma_bf16(acc[t][j], ah[t], wf[j]);
        }
        __syncthreads();
    }

    #pragma unroll
    for (int t = 0; t < 2; t++) {
        const int m = mB + wm * 32 + t * 16 + (lane >> 2);
        #pragma unroll
        for (int j = 0; j < NT8; j++) {
            const int n = nB + wn * WN + j * 8 + (lane & 3) * 2;
            float2 v0 = make_float2(acc[t][j][0], acc[t][j][1]);
            float2 v1 = make_float2(acc[t][j][2], acc[t][j][3]);
            if (EPI == 1) {
                float b0 = bias[n], b1 = bias[n + 1];
                v0.x += b0; v0.y += b1; v1.x += b0; v1.y += b1;
            }
            if (EPI == 2) {
                float2 p0 = *(const float2*)&pC[(size_t)m * ldc + n];
                float2 p1 = *(const float2*)&pC[(size_t)(m + 8) * ldc + n];
                v0.x += p0.x; v0.y += p0.y; v1.x += p1.x; v1.y += p1.y;
            }
            *(float2*)&pC[(size_t)m * ldc + n]       = v0;
            *(float2*)&pC[(size_t)(m + 8) * ldc + n] = v1;
        }
    }
}

// =====================================================================
// Input layernorm (CIN=7) + patch layout
// =====================================================================
__global__ void k_patchnorm(const float* __restrict__ x,
                            const float* __restrict__ gam,
                            const float* __restrict__ bet)
{
    int idx = blockIdx.x * blockDim.x + threadIdx.x;
    if (idx >= BB * SEQLEN) return;
    int b = idx / SEQLEN, s = idx % SEQLEN;
    const float* xp = x + idx * CINC;
    float sum = 0.f;
    #pragma unroll
    for (int c = 0; c < CINC; c++) sum += xp[c];
    float m = sum * (1.f / CINC);
    float var = 0.f;
    #pragma unroll
    for (int c = 0; c < CINC; c++) { float d = xp[c] - m; var = fmaf(d, d, var); }
    var *= (1.f / CINC);
    float inv = rsqrtf(var + 1e-5f);
    int n = s / PLEN, p = s % PLEN;
    size_t ro = (size_t)(b * NPATCH + n) * KPPAD;
    #pragma unroll
    for (int c = 0; c < CINC; c++) {
        float v = (xp[c] - m) * inv * gam[c] + bet[c];
        __nv_bfloat16 h, l; split1(v, h, l);
        g_pnh[ro + c * PLEN + p] = h;
        g_pnl[ro + c * PLEN + p] = l;
    }
}

// =====================================================================
// Warp-per-row layernorm (width 512). SPLIT=1: bf16 planes; 0: fp32.
// =====================================================================
template<int SPLIT>
__global__ void __launch_bounds__(256)
k_lnw(const float* __restrict__ in, float* __restrict__ outf,
      __nv_bfloat16* __restrict__ oh, __nv_bfloat16* __restrict__ ol,
      const float* __restrict__ gam, const float* __restrict__ bet)
{
    const int row  = blockIdx.x * 8 + (threadIdx.x >> 5);
    const int lane = threadIdx.x & 31;
    const float* x = in + (size_t)row * DMOD;

    float4 v[4];
    float s = 0.f, ss = 0.f;
    #pragma unroll
    for (int i = 0; i < 4; i++) {
        v[i] = *(const float4*)&x[i * 128 + lane * 4];
        s  += v[i].x + v[i].y + v[i].z + v[i].w;
        ss += v[i].x*v[i].x + v[i].y*v[i].y + v[i].z*v[i].z + v[i].w*v[i].w;
    }
    #pragma unroll
    for (int o = 16; o > 0; o >>= 1) {
        s  += __shfl_xor_sync(0xffffffffu, s,  o);
        ss += __shfl_xor_sync(0xffffffffu, ss, o);
    }
    float m   = s * (1.f / DMOD);
    float var = ss * (1.f / DMOD) - m * m;
    float inv = rsqrtf(var + 1e-5f);

    #pragma unroll
    for (int i = 0; i < 4; i++) {
        int c = i * 128 + lane * 4;
        float4 g = *(const float4*)&gam[c];
        float4 bb = *(const float4*)&bet[c];
        float o0 = (v[i].x - m) * inv * g.x + bb.x;
        float o1 = (v[i].y - m) * inv * g.y + bb.y;
        float o2 = (v[i].z - m) * inv * g.z + bb.z;
        float o3 = (v[i].w - m) * inv * g.w + bb.w;
        if (SPLIT) {
            __nv_bfloat16 h0,l0,h1,l1,h2,l2,h3,l3;
            split1(o0,h0,l0); split1(o1,h1,l1);
            split1(o2,h2,l2); split1(o3,h3,l3);
            size_t off = (size_t)row * DMOD + c;
            *(uint2*)&oh[off] = make_uint2(
                (uint32_t)__bfloat16_as_ushort(h0) | ((uint32_t)__bfloat16_as_ushort(h1)<<16),
                (uint32_t)__bfloat16_as_ushort(h2) | ((uint32_t)__bfloat16_as_ushort(h3)<<16));
            *(uint2*)&ol[off] = make_uint2(
                (uint32_t)__bfloat16_as_ushort(l0) | ((uint32_t)__bfloat16_as_ushort(l1)<<16),
                (uint32_t)__bfloat16_as_ushort(l2) | ((uint32_t)__bfloat16_as_ushort(l3)<<16));
        } else {
            *(float4*)&outf[(size_t)row * DMOD + c] = make_float4(o0, o1, o2, o3);
        }
    }
}

// =====================================================================
// Depthwise causal conv (DC=4) + silu -> bf16 hi/lo planes
// =====================================================================
__global__ void k_conv(const float* __restrict__ xz,
                       const float* __restrict__ cw,
                       const float* __restrict__ cb)
{
    int idx = blockIdx.x * blockDim.x + threadIdx.x;
    if (idx >= MROWS * DINNER) return;
    int d  = idx % DINNER;
    int bl = idx / DINNER;
    int l  = bl % NPATCH;
    int b  = bl / NPATCH;
    const float4 w = *(const float4*)(cw + d * 4);
    float acc = cb[d];
    size_t base = (size_t)(b * NPATCH) * 2 * DINNER + d;
    if (l >= 3) acc = fmaf(xz[base + (size_t)(l - 3) * 2 * DINNER], w.x, acc);
    if (l >= 2) acc = fmaf(xz[base + (size_t)(l - 2) * 2 * DINNER], w.y, acc);
    if (l >= 1) acc = fmaf(xz[base + (size_t)(l - 1) * 2 * DINNER], w.z, acc);
    acc = fmaf(xz[base + (size_t)l * 2 * DINNER], w.w, acc);
    float v = acc / (1.f + __expf(-acc));
    __nv_bfloat16 h, lo; split1(v, h, lo);
    g_xch[idx] = h; g_xcl[idx] = lo;
}

// =====================================================================
// dbl split-K reduce: 4 partials -> fp32 dbl
// =====================================================================
__global__ void k_dblred(const float* __restrict__ part)
{
    int idx = blockIdx.x * blockDim.x + threadIdx.x;
    if (idx >= MROWS * 64) return;
    g_dbl[idx] = part[idx] + part[idx + MROWS * 64]
               + part[idx + 2 * MROWS * 64] + part[idx + 3 * MROWS * 64];
}

// =====================================================================
// Selective scan + inline delta GEMM (K=32 from SMEM) + gating.
// 4 lanes per (b,d). Writes y hi/lo planes.
// =====================================================================
__global__ void __launch_bounds__(128)
k_scan(const float* __restrict__ xz,  const float* __restrict__ dbl,
       const float* __restrict__ Wdt, const float* __restrict__ bdt,
       const float* __restrict__ A_log, const float* __restrict__ Dskip)
{
    const int tid  = threadIdx.x;
    const int ng   = tid & 3;
    const int dloc = tid >> 2;
    const int d    = blockIdx.x * 32 + dloc;
    const int b    = blockIdx.y;

    __shared__ float sdbl[16][64];
    __shared__ float swdt[32][33];

    {   // W_dt rows for this block's 32 d's
        int r = tid >> 2, c0 = (tid & 3) * 8;
        #pragma unroll
        for (int j = 0; j < 8; j++)
            swdt[r][c0 + j] = Wdt[(blockIdx.x * 32 + r) * DTRANK + c0 + j];
    }
    const float bv = bdt[d];

    float a[4];
    bool structured = true;
    #pragma unroll
    for (int i = 0; i < 4; i++) {
        int n = ng * 4 + i;
        a[i] = -__expf(A_log[d * NST + n]);
        structured = structured && (fabsf(a[i] + (float)(n + 1)) <= 1e-4f * (float)(n + 1));
    }
    const float Dv = Dskip[d];
    float h[4] = {0.f, 0.f, 0.f, 0.f};

    for (int tt = 0; tt < NPATCH; tt += 16) {
        __syncthreads();
        #pragma unroll
        for (int q = 0; q < 2; q++) {
            int f4 = tid + q * 128;
            int r = f4 >> 4, c4 = f4 & 15;
            *(float4*)&sdbl[r][c4 * 4] =
                *(const float4*)&dbl[(b * NPATCH + tt + r) * 64 + c4 * 4];
        }
        __syncthreads();

        const int row0 = b * NPATCH + tt;
        // prefetch t2 = 0
        float xch_c = __bfloat162float(g_xch[(size_t)row0 * DINNER + d]);
        float xcl_c = __bfloat162float(g_xcl[(size_t)row0 * DINNER + d]);
        float zv_c  = xz[(size_t)row0 * 2 * DINNER + DINNER + d];

        #pragma unroll 4
        for (int t2 = 0; t2 < 16; t2++) {
            float xch_n = 0.f, xcl_n = 0.f, zv_n = 0.f;
            if (t2 < 15) {
                size_t r1 = (size_t)(row0 + t2 + 1);
                xch_n = __bfloat162float(g_xch[r1 * DINNER + d]);
                xcl_n = __bfloat162float(g_xcl[r1 * DINNER + d]);
                zv_n  = xz[r1 * 2 * DINNER + DINNER + d];
            }

            // delta pre-activation: dot(dt, W_dt[d]) + b_dt
            float dot = 0.f;
            #pragma unroll
            for (int j = 0; j < 8; j++)
                dot = fmaf(sdbl[t2][ng * 8 + j], swdt[dloc][ng * 8 + j], dot);
            dot += __shfl_xor_sync(0xffffffffu, dot, 1);
            dot += __shfl_xor_sync(0xffffffffu, dot, 2);
            float xv = dot + bv;

            // q = exp(-softplus(xv)); delta = softplus(xv)
            float q, delta;
            if (xv > 0.f) {
                float e = __expf(-xv);
                q = e / (1.f + e);
                delta = xv + __logf(1.f + e);
            } else {
                float e = __expf(xv);
                q = 1.f / (1.f + e);
                delta = __logf(1.f + e);
            }

            float pw[4];
            if (structured) {
                float q2 = q * q, q4 = q2 * q2;
                float b1 = (ng & 1) ? q4 : 1.f;
                float b2 = (ng & 2) ? q4 * q4 : 1.f;
                float bs = b1 * b2;
                pw[0] = bs * q;      pw[1] = bs * q2;
                pw[2] = bs * q2 * q; pw[3] = bs * q4;
            } else {
                #pragma unroll
                for (int i = 0; i < 4; i++) pw[i] = __expf(delta * a[i]);
            }

            float xcv = xch_c + xcl_c;
            float dx = delta * xcv;
            float acc = 0.f;
            #pragma unroll
            for (int i = 0; i < 4; i++) {
                int n = ng * 4 + i;
                h[i] = fmaf(pw[i], h[i], dx * sdbl[t2][32 + n]);
                acc  = fmaf(h[i], sdbl[t2][48 + n], acc);
            }
            acc += __shfl_xor_sync(0xffffffffu, acc, 1);
            acc += __shfl_xor_sync(0xffffffffu, acc, 2);
            if (ng == 0) {
                float sz = zv_c / (1.f + __expf(-zv_c));
                float yv = (acc + xcv * Dv) * sz;
                __nv_bfloat16 hh, ll; split1(yv, hh, ll);
                size_t di = (size_t)(row0 + t2) * DINNER + d;
                g_yh[di] = hh; g_yl[di] = ll;
            }
            xch_c = xch_n; xcl_c = xcl_n; zv_c = zv_n;
        }
    }
}

// =====================================================================
// Head GEMM1: split-K 128 blocks, thread-per-column
// =====================================================================
__global__ void __launch_bounds__(128)
k_head1(const float* __restrict__ hin, const float* __restrict__ W,
        float* __restrict__ part)
{
    const int z = blockIdx.x;
    const int kbase = z * (KFLAT / HKS);
    const int tid = threadIdx.x;
    __shared__ float shw[128][33];
    __shared__ float shh[8][33];
    float acc[8] = {0.f,0.f,0.f,0.f,0.f,0.f,0.f,0.f};

    for (int kc = 0; kc < KFLAT / HKS; kc += 32) {
        const int k0 = kbase + kc;
        #pragma unroll
        for (int q = 0; q < 8; q++) {
            float4 v = *(const float4*)&W[(size_t)tid * KFLAT + k0 + q * 4];
            shw[tid][q*4+0] = v.x; shw[tid][q*4+1] = v.y;
            shw[tid][q*4+2] = v.z; shw[tid][q*4+3] = v.w;
        }
        if (tid < 64) {
            int b = tid >> 3, qq = tid & 7;
            float4 v = *(const float4*)&hin[(size_t)b * KFLAT + k0 + qq * 4];
            shh[b][qq*4+0] = v.x; shh[b][qq*4+1] = v.y;
            shh[b][qq*4+2] = v.z; shh[b][qq*4+3] = v.w;
        }
        __syncthreads();
        #pragma unroll 8
        for (int kk = 0; kk < 32; kk++) {
            float w = shw[tid][kk];
            #pragma unroll
            for (int b = 0; b < 8; b++)
                acc[b] = fmaf(w, shh[b][kk], acc[b]);
        }
        __syncthreads();
    }
    #pragma unroll
    for (int b = 0; b < 8; b++)
        part[(size_t)z * (BB * 128) + b * 128 + tid] = acc[b];
}

__global__ void __launch_bounds__(128)
k_head2(const float* __restrict__ part, const float* __restrict__ hb1,
        const float* __restrict__ hW2,  const float* __restrict__ hb2,
        float* __restrict__ out)
{
    const int b = blockIdx.x;
    const int tid = threadIdx.x;
    __shared__ float g[128];
    float v = 0.f;
    for (int z = 0; z < HKS; z++)
        v += part[(size_t)z * (BB * 128) + b * 128 + tid];
    v += hb1[tid];
    g[tid] = 0.5f * v * (1.f + erff(v * 0.70710678118654752f));
    __syncthreads();
    if (tid < HPRED) {
        float acc = hb2[tid];
        #pragma unroll 16
        for (int j = 0; j < 128; j++)
            acc = fmaf(g[j], hW2[tid * 128 + j], acc);
        out[b * HPRED + tid] = acc;
    }
}

// =====================================================================
// Launch
// =====================================================================
static void* symaddr(const void* sym)
{
    void* p = nullptr;
    cudaGetSymbolAddress(&p, sym);
    return p;
}

#define STGB(BM, BN) ((2 * (BM) * 40 + 2 * (BN) * 40) * 2)
#define SMSZ(BM, BN) (2 * STGB(BM, BN))

extern "C" void kernel_launch(void* const* d_in, const int* in_sizes, int n_in,
                              void* d_out, int out_size)
{
    const float* x      = (const float*)d_in[0];
    const float* in_g   = (const float*)d_in[1];
    const float* in_b   = (const float*)d_in[2];
    const float* pe_W   = (const float*)d_in[3];
    const float* pe_b   = (const float*)d_in[4];
    const float* ln_g   = (const float*)d_in[5];
    const float* ln_b   = (const float*)d_in[6];
    const float* W_in   = (const float*)d_in[7];
    const float* conv_W = (const float*)d_in[8];
    const float* conv_b = (const float*)d_in[9];
    const float* W_x    = (const float*)d_in[10];
    const float* W_dt   = (const float*)d_in[11];
    const float* b_dt   = (const float*)d_in[12];
    const float* A_log  = (const float*)d_in[13];
    const float* Dskip  = (const float*)d_in[14];
    const float* W_out  = (const float*)d_in[15];
    const float* fn_g   = (const float*)d_in[16];
    const float* fn_b   = (const float*)d_in[17];
    const float* hW1    = (const float*)d_in[18];
    const float* hb1    = (const float*)d_in[19];
    const float* hW2    = (const float*)d_in[20];
    const float* hb2    = (const float*)d_in[21];

    float* ph    = (float*)symaddr(g_h);
    float* pln   = (float*)symaddr(g_ln);
    float* pxz   = (float*)symaddr(g_xz);
    float* pdbl  = (float*)symaddr(g_dbl);
    float* pdblp = (float*)symaddr(g_dblp);
    float* ppart = (float*)symaddr(g_part);

    __nv_bfloat16* pnh = (__nv_bfloat16*)symaddr(g_pnh);
    __nv_bfloat16* pnl = (__nv_bfloat16*)symaddr(g_pnl);
    __nv_bfloat16* lnh = (__nv_bfloat16*)symaddr(g_lnh);
    __nv_bfloat16* lnl = (__nv_bfloat16*)symaddr(g_lnl);
    __nv_bfloat16* xch = (__nv_bfloat16*)symaddr(g_xch);
    __nv_bfloat16* xcl = (__nv_bfloat16*)symaddr(g_xcl);
    __nv_bfloat16* yh  = (__nv_bfloat16*)symaddr(g_yh);
    __nv_bfloat16* yl  = (__nv_bfloat16*)symaddr(g_yl);

    __nv_bfloat16* peWh = (__nv_bfloat16*)symaddr(g_peWh);
    __nv_bfloat16* peWl = (__nv_bfloat16*)symaddr(g_peWl);
    __nv_bfloat16* Winh = (__nv_bfloat16*)symaddr(g_Winh);
    __nv_bfloat16* Winl = (__nv_bfloat16*)symaddr(g_Winl);
    __nv_bfloat16* Wxh  = (__nv_bfloat16*)symaddr(g_Wxh);
    __nv_bfloat16* Wxl  = (__nv_bfloat16*)symaddr(g_Wxl);
    __nv_bfloat16* Wouth= (__nv_bfloat16*)symaddr(g_Wouth);
    __nv_bfloat16* Woutl= (__nv_bfloat16*)symaddr(g_Woutl);

    static bool attr_done = false;
    if (!attr_done) {
        cudaFuncSetAttribute(bgemm<128,128,0>, cudaFuncAttributeMaxDynamicSharedMemorySize, SMSZ(128,128));
        cudaFuncSetAttribute(bgemm<64,128,1>,  cudaFuncAttributeMaxDynamicSharedMemorySize, SMSZ(64,128));
        cudaFuncSetAttribute(bgemm<64,128,2>,  cudaFuncAttributeMaxDynamicSharedMemorySize, SMSZ(64,128));
        cudaFuncSetAttribute(bgemm<64,64,0>,   cudaFuncAttributeMaxDynamicSharedMemorySize, SMSZ(64,64));
        attr_done = true;
    }

    // 0) fused weight split
    k_splitall<<<1024, 256>>>(pe_W, W_in, W_x, W_out);

    // 1) input LN + patch planes
    k_patchnorm<<<(BB * SEQLEN + 255) / 256, 256>>>(x, in_g, in_b);

    // 2) patch embed (2048x512, K=128 padded)
    bgemm<64,128,1><<<dim3(DMOD/128, MROWS/64), 256, SMSZ(64,128)>>>(
        MROWS, DMOD, KPPAD, pnh, pnl, KPPAD, peWh, peWl, KPPAD, pe_b, ph, DMOD, 0);

    // 3) Mamba layers
    for (int i = 0; i < NLAY; i++) {
        k_lnw<1><<<MROWS/8, 256>>>(ph, nullptr, lnh, lnl,
                                   ln_g + i * DMOD, ln_b + i * DMOD);

        // xz = ln @ W_in^T  (2048 x 2048, K=512)
        bgemm<128,128,0><<<dim3(2*DINNER/128, MROWS/128), 256, SMSZ(128,128)>>>(
            MROWS, 2*DINNER, DMOD, lnh, lnl, DMOD,
            Winh + (size_t)i*2*DINNER*DMOD, Winl + (size_t)i*2*DINNER*DMOD, DMOD,
            nullptr, pxz, 2*DINNER, 0);

        k_conv<<<(MROWS * DINNER + 255) / 256, 256>>>(
            pxz, conv_W + (size_t)i*DINNER*DCONV, conv_b + (size_t)i*DINNER);

        // dbl partial = xc @ W_x^T  (2048 x 64, K split 4 x 256)
        bgemm<64,64,0><<<dim3(1, MROWS/64, DBLKS), 256, SMSZ(64,64)>>>(
            MROWS, 64, DINNER/DBLKS, xch, xcl, DINNER,
            Wxh + (size_t)i*64*DINNER, Wxl + (size_t)i*64*DINNER, DINNER,
            nullptr, pdblp, 64, MROWS*64);
        k_dblred<<<(MROWS*64 + 255) / 256, 256>>>(pdblp);

        // scan (inline delta GEMM) -> y planes
        k_scan<<<dim3(DINNER/32, BB), 128>>>(
            pxz, pdbl,
            W_dt + (size_t)i*DINNER*DTRANK, b_dt + (size_t)i*DINNER,
            A_log + (size_t)i*DINNER*NST, Dskip + (size_t)i*DINNER);

        // h += y @ W_out^T  (2048 x 512, K=1024)
        bgemm<64,128,2><<<dim3(DMOD/128, MROWS/64), 256, SMSZ(64,128)>>>(
            MROWS, DMOD, DINNER, yh, yl, DINNER,
            Wouth + (size_t)i*DMOD*DINNER, Woutl + (size_t)i*DMOD*DINNER, DINNER,
            nullptr, ph, DMOD, 0);
    }

    // 4) final LN (fp32 for head)
    k_lnw<0><<<MROWS/8, 256>>>(ph, pln, nullptr, nullptr, fn_g, fn_b);

    // 5) head
    k_head1<<<HKS, 128>>>(pln, hW1, ppart);
    k_head2<<<BB, 128>>>(ppart, hb1, hW2, hb2, (float*)d_out);
}

// round 8
// speedup vs baseline: 2.0130x; 1.0757x over previous
#include <cuda_runtime.h>
#include <cuda_bf16.h>
#include <math.h>
#include <stdint.h>

// ---------------- Problem constants ----------------
#define BB      8
#define SEQLEN  4096
#define CINC    7
#define DMOD    512
#define NLAY    4
#define PLEN    16
#define NPATCH  256
#define NST     16
#define DCONV   4
#define DINNER  1024
#define DTRANK  32
#define MROWS   (BB*NPATCH)    // 2048
#define KPATCH  112
#define KPPAD   128
#define HPRED   96
#define HKS     256
#define KFLAT   (NPATCH*DMOD)  // 131072
#define DBLKS   4

// ---------------- fp32 scratch ----------------
__device__ float g_h   [MROWS*DMOD];
__device__ float g_ln  [MROWS*DMOD];
__device__ float g_xz  [MROWS*2*DINNER];
__device__ float g_dblp[DBLKS*MROWS*64];
__device__ float g_part[HKS*BB*128];

// ---------------- bf16 hi/lo activation planes ----------------
__device__ __nv_bfloat16 g_pnh[MROWS*KPPAD],  g_pnl[MROWS*KPPAD];
__device__ __nv_bfloat16 g_lnh[MROWS*DMOD],   g_lnl[MROWS*DMOD];
__device__ __nv_bfloat16 g_xch[MROWS*DINNER], g_xcl[MROWS*DINNER];
__device__ __nv_bfloat16 g_yh [MROWS*DINNER], g_yl [MROWS*DINNER];

// ---------------- bf16 hi/lo weight planes ----------------
__device__ __nv_bfloat16 g_peWh[DMOD*KPPAD],         g_peWl[DMOD*KPPAD];
__device__ __nv_bfloat16 g_Winh[NLAY*2*DINNER*DMOD], g_Winl[NLAY*2*DINNER*DMOD];
__device__ __nv_bfloat16 g_Wxh [NLAY*64*DINNER],     g_Wxl [NLAY*64*DINNER];
__device__ __nv_bfloat16 g_Wouth[NLAY*DMOD*DINNER],  g_Woutl[NLAY*DMOD*DINNER];

#define NWIN  (NLAY*2*DINNER*DMOD)   // 4194304
#define NWOUT (NLAY*DMOD*DINNER)     // 2097152
#define NWX   (NLAY*64*DINNER)       // 262144

// =====================================================================
// Helpers
// =====================================================================
static __device__ __forceinline__ uint32_t smem_u32(const void* p) {
    uint32_t a;
    asm("{ .reg .u64 t; cvta.to.shared.u64 t, %1; cvt.u32.u64 %0, t; }"
        : "=r"(a) : "l"(p));
    return a;
}
static __device__ __forceinline__ void ldm_x4(uint32_t* r, uint32_t addr) {
    asm volatile("ldmatrix.sync.aligned.m8n8.x4.shared.b16 {%0,%1,%2,%3}, [%4];"
        : "=r"(r[0]), "=r"(r[1]), "=r"(r[2]), "=r"(r[3]) : "r"(addr));
}
static __device__ __forceinline__ void mma_bf16(float* c, const uint32_t* a,
                                                const uint32_t* b) {
    asm volatile(
        "mma.sync.aligned.m16n8k16.row.col.f32.bf16.bf16.f32 "
        "{%0,%1,%2,%3}, {%4,%5,%6,%7}, {%8,%9}, {%0,%1,%2,%3};"
        : "+f"(c[0]), "+f"(c[1]), "+f"(c[2]), "+f"(c[3])
        : "r"(a[0]), "r"(a[1]), "r"(a[2]), "r"(a[3]), "r"(b[0]), "r"(b[1]));
}
static __device__ __forceinline__ void cp16(uint32_t dst, const void* src) {
    asm volatile("cp.async.cg.shared.global [%0], [%1], 16;"
                 :: "r"(dst), "l"(src));
}
static __device__ __forceinline__ void cp_commit() {
    asm volatile("cp.async.commit_group;");
}
template<int NW> static __device__ __forceinline__ void cp_wait() {
    asm volatile("cp.async.wait_group %0;" :: "n"(NW));
}
static __device__ __forceinline__ void split1(float v, __nv_bfloat16& h, __nv_bfloat16& l) {
    h = __float2bfloat16(v);
    l = __float2bfloat16(v - __bfloat162float(h));
}
static __device__ __forceinline__ uint32_t pk2(__nv_bfloat16 a, __nv_bfloat16 b) {
    return (uint32_t)__bfloat16_as_ushort(a) | ((uint32_t)__bfloat16_as_ushort(b) << 16);
}
static __device__ __forceinline__ void split4v(float4 v, uint2& h, uint2& l) {
    __nv_bfloat16 h0,l0,h1,l1,h2,l2,h3,l3;
    split1(v.x,h0,l0); split1(v.y,h1,l1); split1(v.z,h2,l2); split1(v.w,h3,l3);
    h = make_uint2(pk2(h0,h1), pk2(h2,h3));
    l = make_uint2(pk2(l0,l1), pk2(l2,l3));
}

// =====================================================================
// Fused weight split v2: vectorized, one flat index space
// =====================================================================
__global__ void __launch_bounds__(256)
k_splitall(const float* __restrict__ peW, const float* __restrict__ Win,
           const float* __restrict__ Wx,  const float* __restrict__ Wout)
{
    const int t0 = blockIdx.x * blockDim.x + threadIdx.x;
    const int stride = gridDim.x * blockDim.x;
    constexpr int T1 = NWIN / 4;                 // Win f4s
    constexpr int T2 = T1 + NWOUT / 4;
    constexpr int T3 = T2 + NWX / 4;

    for (int i4 = t0; i4 < T3; i4 += stride) {
        const float* src; __nv_bfloat16 *dh, *dl; int off;
        if (i4 < T1)      { src = Win;  dh = g_Winh;  dl = g_Winl;  off = i4; }
        else if (i4 < T2) { src = Wout; dh = g_Wouth; dl = g_Woutl; off = i4 - T1; }
        else              { src = Wx;   dh = g_Wxh;   dl = g_Wxl;   off = i4 - T2; }
        float4 v = *(const float4*)&src[(size_t)off * 4];
        uint2 h, l; split4v(v, h, l);
        *(uint2*)&dh[(size_t)off * 4] = h;
        *(uint2*)&dl[(size_t)off * 4] = l;
    }
    // peW: 512 x 112 -> padded ld 128
    for (int i4 = t0; i4 < DMOD * (KPATCH / 4); i4 += stride) {
        int r = i4 / (KPATCH / 4), c4 = i4 % (KPATCH / 4);
        float4 v = *(const float4*)&peW[(size_t)r * KPATCH + c4 * 4];
        uint2 h, l; split4v(v, h, l);
        *(uint2*)&g_peWh[(size_t)r * KPPAD + c4 * 4] = h;
        *(uint2*)&g_peWl[(size_t)r * KPPAD + c4 * 4] = l;
    }
}

// =====================================================================
// bf16x3 mma.sync GEMM, cp.async pipelined, pre-split bf16 inputs.
// =====================================================================
template<int BM, int BN, int EPI>
__global__ void __launch_bounds__(256, 2)
bgemm(int M, int N, int Ks,
      const __nv_bfloat16* __restrict__ Ah, const __nv_bfloat16* __restrict__ Al, int lda,
      const __nv_bfloat16* __restrict__ Wh, const __nv_bfloat16* __restrict__ Wl, int ldw,
      const float* __restrict__ bias, float* __restrict__ C, int ldc, int sliceC)
{
    constexpr int LDS = 40;
    constexpr int WNW = (BM == 128) ? 2 : 4;
    constexpr int WN  = BN / WNW;
    constexpr int NT8 = WN / 8;
    constexpr int APL = BM * LDS, WPL = BN * LDS;
    constexpr int STG = 2 * APL + 2 * WPL;

    extern __shared__ __nv_bfloat16 sm[];
    const uint32_t smu = smem_u32(sm);

    const int tid = threadIdx.x, lane = tid & 31, warp = tid >> 5;
    const int wn = warp % WNW, wm = warp / WNW;
    const int mB = blockIdx.y * BM, nB = blockIdx.x * BN;
    const int kbase = blockIdx.z * Ks;
    float* pC = C + (size_t)blockIdx.z * sliceC;

    float acc[2][NT8][4];
    #pragma unroll
    for (int t = 0; t < 2; t++)
        #pragma unroll
        for (int j = 0; j < NT8; j++)
            #pragma unroll
            for (int r = 0; r < 4; r++) acc[t][j][r] = 0.f;

    const int nCh = Ks / 32;

    auto load_stage = [&](int s) {
        const uint32_t sb = smu + (uint32_t)((s & 1) * STG) * 2;
        const int k0 = kbase + s * 32;
        #pragma unroll
        for (int i = tid; i < BM * 4; i += 256) {
            int row = i >> 2, c = i & 3;
            size_t g = (size_t)(mB + row) * lda + k0 + c * 8;
            uint32_t d = sb + (uint32_t)(row * LDS + c * 8) * 2;
            cp16(d, Ah + g);
            cp16(d + APL * 2, Al + g);
        }
        #pragma unroll
        for (int i = tid; i < BN * 4; i += 256) {
            int row = i >> 2, c = i & 3;
            size_t g = (size_t)(nB + row) * ldw + k0 + c * 8;
            uint32_t d = sb + (uint32_t)(2 * APL + row * LDS + c * 8) * 2;
            cp16(d, Wh + g);
            cp16(d + WPL * 2, Wl + g);
        }
        cp_commit();
    };

    load_stage(0);

    for (int s = 0; s < nCh; s++) {
        if (s + 1 < nCh) { load_stage(s + 1); cp_wait<1>(); }
        else             { cp_wait<0>(); }
        __syncthreads();

        const uint32_t sb = smu + (uint32_t)((s & 1) * STG) * 2;
        #pragma unroll
        for (int k16 = 0; k16 < 2; k16++) {
            uint32_t ah[2][4], al[2][4], wf[NT8][2];
            const int arow = wm * 32 + (lane & 15);
            const int acol = k16 * 16 + (lane >> 4) * 8;
            const uint32_t aAddr = sb + (uint32_t)(arow * LDS + acol) * 2;
            ldm_x4(ah[0], aAddr);
            ldm_x4(ah[1], aAddr + 16 * LDS * 2);

            const int wrow = wn * WN + ((lane >> 4) << 3) + (lane & 7);
            const int wcol = k16 * 16 + ((lane >> 3) & 1) * 8;
            const uint32_t wAddr = sb + (uint32_t)(2 * APL + wrow * LDS + wcol) * 2;
            #pragma unroll
            for (int jp = 0; jp < NT8 / 2; jp++) {
                uint32_t t4[4];
                ldm_x4(t4, wAddr + jp * 16 * LDS * 2);
                wf[2*jp][0] = t4[0]; wf[2*jp][1] = t4[1];
                wf[2*jp+1][0] = t4[2]; wf[2*jp+1][1] = t4[3];
            }
            #pragma unroll
            for (int t = 0; t < 2; t++)
                #pragma unroll
                for (int j = 0; j < NT8; j++) mma_bf16(acc[t][j], ah[t], wf[j]);

            ldm_x4(al[0], aAddr + APL * 2);
            ldm_x4(al[1], aAddr + APL * 2 + 16 * LDS * 2);
            #pragma unroll
            for (int t = 0; t < 2; t++)
                #pragma unroll
                for (int j = 0; j < NT8; j++) mma_bf16(acc[t][j], al[t], wf[j]);

            #pragma unroll
            for (int jp = 0; jp < NT8 / 2; jp++) {
                uint32_t t4[4];
                ldm_x4(t4, wAddr + WPL * 2 + jp * 16 * LDS * 2);
                wf[2*jp][0] = t4[0]; wf[2*jp][1] = t4[1];
                wf[2*jp+1][0] = t4[2]; wf[2*jp+1][1] = t4[3];
            }
            #pragma unroll
            for (int t = 0; t < 2; t++)
                #pragma unroll
                for (int j = 0; j < NT8; j++) mma_bf16(acc[t][j], ah[t], wf[j]);
        }
        __syncthreads();
    }

    #pragma unroll
    for (int t = 0; t < 2; t++) {
        const int m = mB + wm * 32 + t * 16 + (lane >> 2);
        #pragma unroll
        for (int j = 0; j < NT8; j++) {
            const int n = nB + wn * WN + j * 8 + (lane & 3) * 2;
            float2 v0 = make_float2(acc[t][j][0], acc[t][j][1]);
            float2 v1 = make_float2(acc[t][j][2], acc[t][j][3]);
            if (EPI == 1) {
                float b0 = bias[n], b1 = bias[n + 1];
                v0.x += b0; v0.y += b1; v1.x += b0; v1.y += b1;
            }
            if (EPI == 2) {
                float2 p0 = *(const float2*)&pC[(size_t)m * ldc + n];
                float2 p1 = *(const float2*)&pC[(size_t)(m + 8) * ldc + n];
                v0.x += p0.x; v0.y += p0.y; v1.x += p1.x; v1.y += p1.y;
            }
            *(float2*)&pC[(size_t)m * ldc + n]       = v0;
            *(float2*)&pC[(size_t)(m + 8) * ldc + n] = v1;
        }
    }
}

// =====================================================================
// Input layernorm (CIN=7) + patch layout
// =====================================================================
__global__ void k_patchnorm(const float* __restrict__ x,
                            const float* __restrict__ gam,
                            const float* __restrict__ bet)
{
    int idx = blockIdx.x * blockDim.x + threadIdx.x;
    if (idx >= BB * SEQLEN) return;
    int b = idx / SEQLEN, s = idx % SEQLEN;
    const float* xp = x + idx * CINC;
    float sum = 0.f;
    #pragma unroll
    for (int c = 0; c < CINC; c++) sum += xp[c];
    float m = sum * (1.f / CINC);
    float var = 0.f;
    #pragma unroll
    for (int c = 0; c < CINC; c++) { float d = xp[c] - m; var = fmaf(d, d, var); }
    var *= (1.f / CINC);
    float inv = rsqrtf(var + 1e-5f);
    int n = s / PLEN, p = s % PLEN;
    size_t ro = (size_t)(b * NPATCH + n) * KPPAD;
    #pragma unroll
    for (int c = 0; c < CINC; c++) {
        float v = (xp[c] - m) * inv * gam[c] + bet[c];
        __nv_bfloat16 h, l; split1(v, h, l);
        g_pnh[ro + c * PLEN + p] = h;
        g_pnl[ro + c * PLEN + p] = l;
    }
}

// =====================================================================
// Warp-per-row layernorm (width 512). SPLIT=1: bf16 planes; 0: fp32.
// =====================================================================
template<int SPLIT>
__global__ void __launch_bounds__(256)
k_lnw(const float* __restrict__ in, float* __restrict__ outf,
      __nv_bfloat16* __restrict__ oh, __nv_bfloat16* __restrict__ ol,
      const float* __restrict__ gam, const float* __restrict__ bet)
{
    const int row  = blockIdx.x * 8 + (threadIdx.x >> 5);
    const int lane = threadIdx.x & 31;
    const float* x = in + (size_t)row * DMOD;

    float4 v[4];
    float s = 0.f, ss = 0.f;
    #pragma unroll
    for (int i = 0; i < 4; i++) {
        v[i] = *(const float4*)&x[i * 128 + lane * 4];
        s  += v[i].x + v[i].y + v[i].z + v[i].w;
        ss += v[i].x*v[i].x + v[i].y*v[i].y + v[i].z*v[i].z + v[i].w*v[i].w;
    }
    #pragma unroll
    for (int o = 16; o > 0; o >>= 1) {
        s  += __shfl_xor_sync(0xffffffffu, s,  o);
        ss += __shfl_xor_sync(0xffffffffu, ss, o);
    }
    float m   = s * (1.f / DMOD);
    float var = ss * (1.f / DMOD) - m * m;
    float inv = rsqrtf(var + 1e-5f);

    #pragma unroll
    for (int i = 0; i < 4; i++) {
        int c = i * 128 + lane * 4;
        float4 g = *(const float4*)&gam[c];
        float4 bb = *(const float4*)&bet[c];
        float o0 = (v[i].x - m) * inv * g.x + bb.x;
        float o1 = (v[i].y - m) * inv * g.y + bb.y;
        float o2 = (v[i].z - m) * inv * g.z + bb.z;
        float o3 = (v[i].w - m) * inv * g.w + bb.w;
        if (SPLIT) {
            float4 vv = make_float4(o0, o1, o2, o3);
            uint2 h, l; split4v(vv, h, l);
            size_t off = (size_t)row * DMOD + c;
            *(uint2*)&oh[off] = h;
            *(uint2*)&ol[off] = l;
        } else {
            *(float4*)&outf[(size_t)row * DMOD + c] = make_float4(o0, o1, o2, o3);
        }
    }
}

// =====================================================================
// Depthwise causal conv (DC=4) + silu -> bf16 hi/lo planes
// =====================================================================
__global__ void k_conv(const float* __restrict__ xz,
                       const float* __restrict__ cw,
                       const float* __restrict__ cb)
{
    int idx = blockIdx.x * blockDim.x + threadIdx.x;
    if (idx >= MROWS * DINNER) return;
    int d  = idx % DINNER;
    int bl = idx / DINNER;
    int l  = bl % NPATCH;
    int b  = bl / NPATCH;
    const float4 w = *(const float4*)(cw + d * 4);
    float acc = cb[d];
    size_t base = (size_t)(b * NPATCH) * 2 * DINNER + d;
    if (l >= 3) acc = fmaf(xz[base + (size_t)(l - 3) * 2 * DINNER], w.x, acc);
    if (l >= 2) acc = fmaf(xz[base + (size_t)(l - 2) * 2 * DINNER], w.y, acc);
    if (l >= 1) acc = fmaf(xz[base + (size_t)(l - 1) * 2 * DINNER], w.z, acc);
    acc = fmaf(xz[base + (size_t)l * 2 * DINNER], w.w, acc);
    float v = acc / (1.f + __expf(-acc));
    __nv_bfloat16 h, lo; split1(v, h, lo);
    g_xch[idx] = h; g_xcl[idx] = lo;
}

// =====================================================================
// Selective scan + inline delta GEMM + fused dbl split-K reduce + gating
// 4 lanes per (b,d). Writes y hi/lo planes.
// =====================================================================
__global__ void __launch_bounds__(128)
k_scan(const float* __restrict__ xz,  const float* __restrict__ dblp,
       const float* __restrict__ Wdt, const float* __restrict__ bdt,
       const float* __restrict__ A_log, const float* __restrict__ Dskip)
{
    const int tid  = threadIdx.x;
    const int ng   = tid & 3;
    const int dloc = tid >> 2;
    const int d    = blockIdx.x * 32 + dloc;
    const int b    = blockIdx.y;

    __shared__ float sdbl[16][64];
    __shared__ float swdt[32][33];

    {
        int r = tid >> 2, c0 = (tid & 3) * 8;
        #pragma unroll
        for (int j = 0; j < 8; j++)
            swdt[r][c0 + j] = Wdt[(blockIdx.x * 32 + r) * DTRANK + c0 + j];
    }
    const float bv = bdt[d];

    float a[4];
    bool structured = true;
    #pragma unroll
    for (int i = 0; i < 4; i++) {
        int n = ng * 4 + i;
        a[i] = -__expf(A_log[d * NST + n]);
        structured = structured && (fabsf(a[i] + (float)(n + 1)) <= 1e-4f * (float)(n + 1));
    }
    const float Dv = Dskip[d];
    float h[4] = {0.f, 0.f, 0.f, 0.f};

    for (int tt = 0; tt < NPATCH; tt += 16) {
        __syncthreads();
        #pragma unroll
        for (int q = 0; q < 2; q++) {
            int f4 = tid + q * 128;
            int r = f4 >> 4, c4 = f4 & 15;
            size_t gi = (size_t)(b * NPATCH + tt + r) * 64 + c4 * 4;
            float4 v0 = *(const float4*)&dblp[gi];
            float4 v1 = *(const float4*)&dblp[gi + (size_t)MROWS * 64];
            float4 v2 = *(const float4*)&dblp[gi + (size_t)2 * MROWS * 64];
            float4 v3 = *(const float4*)&dblp[gi + (size_t)3 * MROWS * 64];
            *(float4*)&sdbl[r][c4 * 4] = make_float4(
                v0.x + v1.x + v2.x + v3.x, v0.y + v1.y + v2.y + v3.y,
                v0.z + v1.z + v2.z + v3.z, v0.w + v1.w + v2.w + v3.w);
        }
        __syncthreads();

        const int row0 = b * NPATCH + tt;
        float xch_c = __bfloat162float(g_xch[(size_t)row0 * DINNER + d]);
        float xcl_c = __bfloat162float(g_xcl[(size_t)row0 * DINNER + d]);
        float zv_c  = xz[(size_t)row0 * 2 * DINNER + DINNER + d];

        #pragma unroll 4
        for (int t2 = 0; t2 < 16; t2++) {
            float xch_n = 0.f, xcl_n = 0.f, zv_n = 0.f;
            if (t2 < 15) {
                size_t r1 = (size_t)(row0 + t2 + 1);
                xch_n = __bfloat162float(g_xch[r1 * DINNER + d]);
                xcl_n = __bfloat162float(g_xcl[r1 * DINNER + d]);
                zv_n  = xz[r1 * 2 * DINNER + DINNER + d];
            }

            float dot = 0.f;
            #pragma unroll
            for (int j = 0; j < 8; j++)
                dot = fmaf(sdbl[t2][ng * 8 + j], swdt[dloc][ng * 8 + j], dot);
            dot += __shfl_xor_sync(0xffffffffu, dot, 1);
            dot += __shfl_xor_sync(0xffffffffu, dot, 2);
            float xv = dot + bv;

            float q, delta;
            if (xv > 0.f) {
                float e = __expf(-xv);
                q = e / (1.f + e);
                delta = xv + __logf(1.f + e);
            } else {
                float e = __expf(xv);
                q = 1.f / (1.f + e);
                delta = __logf(1.f + e);
            }

            float pw[4];
            if (structured) {
                float q2 = q * q, q4 = q2 * q2;
                float b1 = (ng & 1) ? q4 : 1.f;
                float b2 = (ng & 2) ? q4 * q4 : 1.f;
                float bs = b1 * b2;
                pw[0] = bs * q;      pw[1] = bs * q2;
                pw[2] = bs * q2 * q; pw[3] = bs * q4;
            } else {
                #pragma unroll
                for (int i = 0; i < 4; i++) pw[i] = __expf(delta * a[i]);
            }

            float xcv = xch_c + xcl_c;
            float dx = delta * xcv;
            float acc = 0.f;
            #pragma unroll
            for (int i = 0; i < 4; i++) {
                int n = ng * 4 + i;
                h[i] = fmaf(pw[i], h[i], dx * sdbl[t2][32 + n]);
                acc  = fmaf(h[i], sdbl[t2][48 + n], acc);
            }
            acc += __shfl_xor_sync(0xffffffffu, acc, 1);
            acc += __shfl_xor_sync(0xffffffffu, acc, 2);
            if (ng == 0) {
                float sz = zv_c / (1.f + __expf(-zv_c));
                float yv = (acc + xcv * Dv) * sz;
                __nv_bfloat16 hh, ll; split1(yv, hh, ll);
                size_t di = (size_t)(row0 + t2) * DINNER + d;
                g_yh[di] = hh; g_yl[di] = ll;
            }
            xch_c = xch_n; xcl_c = xcl_n; zv_c = zv_n;
        }
    }
}

// =====================================================================
// Head GEMM1 v2: 256 split-K blocks, coalesced W staging, 256 threads
// thread = (g, j): batches g*4..g*4+3, column j
// =====================================================================
__global__ void __launch_bounds__(256)
k_head1(const float* __restrict__ hin, const float* __restrict__ W,
        float* __restrict__ part)
{
    const int z = blockIdx.x;
    const int kbase = z * (KFLAT / HKS);       // 512-wide chunk
    const int tid = threadIdx.x;
    const int j = tid & 127, g = tid >> 7;     // g in {0,1}
    __shared__ float shw[128][65];
    __shared__ float shh[8][65];
    float acc[4] = {0.f, 0.f, 0.f, 0.f};

    for (int kc = 0; kc < KFLAT / HKS; kc += 64) {
        const int k0 = kbase + kc;
        // W tile: 128 rows x 64 cols, coalesced f4 loads
        #pragma unroll
        for (int i = tid; i < 128 * 16; i += 256) {
            int r = i >> 4, c4 = i & 15;
            float4 v = *(const float4*)&W[(size_t)r * KFLAT + k0 + c4 * 4];
            shw[r][c4*4+0] = v.x; shw[r][c4*4+1] = v.y;
            shw[r][c4*4+2] = v.z; shw[r][c4*4+3] = v.w;
        }
        if (tid < 128) {
            int r = tid >> 4, c4 = tid & 15;
            float4 v = *(const float4*)&hin[(size_t)r * KFLAT + k0 + c4 * 4];
            shh[r][c4*4+0] = v.x; shh[r][c4*4+1] = v.y;
            shh[r][c4*4+2] = v.z; shh[r][c4*4+3] = v.w;
        }
        __syncthreads();
        #pragma unroll 8
        for (int kk = 0; kk < 64; kk++) {
            float w = shw[j][kk];
            #pragma unroll
            for (int bq = 0; bq < 4; bq++)
                acc[bq] = fmaf(w, shh[g * 4 + bq][kk], acc[bq]);
        }
        __syncthreads();
    }
    #pragma unroll
    for (int bq = 0; bq < 4; bq++)
        part[(size_t)z * (BB * 128) + (g * 4 + bq) * 128 + j] = acc[bq];
}

__global__ void __launch_bounds__(128)
k_head2(const float* __restrict__ part, const float* __restrict__ hb1,
        const float* __restrict__ hW2,  const float* __restrict__ hb2,
        float* __restrict__ out)
{
    const int b = blockIdx.x;
    const int tid = threadIdx.x;
    __shared__ float g[128];
    float v = 0.f;
    for (int z = 0; z < HKS; z++)
        v += part[(size_t)z * (BB * 128) + b * 128 + tid];
    v += hb1[tid];
    g[tid] = 0.5f * v * (1.f + erff(v * 0.70710678118654752f));
    __syncthreads();
    if (tid < HPRED) {
        float acc = hb2[tid];
        #pragma unroll 16
        for (int j = 0; j < 128; j++)
            acc = fmaf(g[j], hW2[tid * 128 + j], acc);
        out[b * HPRED + tid] = acc;
    }
}

// =====================================================================
// Launch
// =====================================================================
static void* symaddr(const void* sym)
{
    void* p = nullptr;
    cudaGetSymbolAddress(&p, sym);
    return p;
}

#define STGB(BM, BN) ((2 * (BM) * 40 + 2 * (BN) * 40) * 2)
#define SMSZ(BM, BN) (2 * STGB(BM, BN))

extern "C" void kernel_launch(void* const* d_in, const int* in_sizes, int n_in,
                              void* d_out, int out_size)
{
    const float* x      = (const float*)d_in[0];
    const float* in_g   = (const float*)d_in[1];
    const float* in_b   = (const float*)d_in[2];
    const float* pe_W   = (const float*)d_in[3];
    const float* pe_b   = (const float*)d_in[4];
    const float* ln_g   = (const float*)d_in[5];
    const float* ln_b   = (const float*)d_in[6];
    const float* W_in   = (const float*)d_in[7];
    const float* conv_W = (const float*)d_in[8];
    const float* conv_b = (const float*)d_in[9];
    const float* W_x    = (const float*)d_in[10];
    const float* W_dt   = (const float*)d_in[11];
    const float* b_dt   = (const float*)d_in[12];
    const float* A_log  = (const float*)d_in[13];
    const float* Dskip  = (const float*)d_in[14];
    const float* W_out  = (const float*)d_in[15];
    const float* fn_g   = (const float*)d_in[16];
    const float* fn_b   = (const float*)d_in[17];
    const float* hW1    = (const float*)d_in[18];
    const float* hb1    = (const float*)d_in[19];
    const float* hW2    = (const float*)d_in[20];
    const float* hb2    = (const float*)d_in[21];

    float* ph    = (float*)symaddr(g_h);
    float* pln   = (float*)symaddr(g_ln);
    float* pxz   = (float*)symaddr(g_xz);
    float* pdblp = (float*)symaddr(g_dblp);
    float* ppart = (float*)symaddr(g_part);

    __nv_bfloat16* pnh = (__nv_bfloat16*)symaddr(g_pnh);
    __nv_bfloat16* pnl = (__nv_bfloat16*)symaddr(g_pnl);
    __nv_bfloat16* lnh = (__nv_bfloat16*)symaddr(g_lnh);
    __nv_bfloat16* lnl = (__nv_bfloat16*)symaddr(g_lnl);
    __nv_bfloat16* xch = (__nv_bfloat16*)symaddr(g_xch);
    __nv_bfloat16* xcl = (__nv_bfloat16*)symaddr(g_xcl);
    __nv_bfloat16* yh  = (__nv_bfloat16*)symaddr(g_yh);
    __nv_bfloat16* yl  = (__nv_bfloat16*)symaddr(g_yl);

    __nv_bfloat16* peWh = (__nv_bfloat16*)symaddr(g_peWh);
    __nv_bfloat16* peWl = (__nv_bfloat16*)symaddr(g_peWl);
    __nv_bfloat16* Winh = (__nv_bfloat16*)symaddr(g_Winh);
    __nv_bfloat16* Winl = (__nv_bfloat16*)symaddr(g_Winl);
    __nv_bfloat16* Wxh  = (__nv_bfloat16*)symaddr(g_Wxh);
    __nv_bfloat16* Wxl  = (__nv_bfloat16*)symaddr(g_Wxl);
    __nv_bfloat16* Wouth= (__nv_bfloat16*)symaddr(g_Wouth);
    __nv_bfloat16* Woutl= (__nv_bfloat16*)symaddr(g_Woutl);

    static bool attr_done = false;
    if (!attr_done) {
        cudaFuncSetAttribute(bgemm<128,128,0>, cudaFuncAttributeMaxDynamicSharedMemorySize, SMSZ(128,128));
        cudaFuncSetAttribute(bgemm<64,128,1>,  cudaFuncAttributeMaxDynamicSharedMemorySize, SMSZ(64,128));
        cudaFuncSetAttribute(bgemm<64,128,2>,  cudaFuncAttributeMaxDynamicSharedMemorySize, SMSZ(64,128));
        cudaFuncSetAttribute(bgemm<64,64,0>,   cudaFuncAttributeMaxDynamicSharedMemorySize, SMSZ(64,64));
        attr_done = true;
    }

    // 0) fused weight split
    k_splitall<<<1024, 256>>>(pe_W, W_in, W_x, W_out);

    // 1) input LN + patch planes
    k_patchnorm<<<(BB * SEQLEN + 255) / 256, 256>>>(x, in_g, in_b);

    // 2) patch embed (2048x512, K=128 padded)
    bgemm<64,128,1><<<dim3(DMOD/128, MROWS/64), 256, SMSZ(64,128)>>>(
        MROWS, DMOD, KPPAD, pnh, pnl, KPPAD, peWh, peWl, KPPAD, pe_b, ph, DMOD, 0);

    // 3) Mamba layers
    for (int i = 0; i < NLAY; i++) {
        k_lnw<1><<<MROWS/8, 256>>>(ph, nullptr, lnh, lnl,
                                   ln_g + i * DMOD, ln_b + i * DMOD);

        // xz = ln @ W_in^T  (2048 x 2048, K=512)
        bgemm<128,128,0><<<dim3(2*DINNER/128, MROWS/128), 256, SMSZ(128,128)>>>(
            MROWS, 2*DINNER, DMOD, lnh, lnl, DMOD,
            Winh + (size_t)i*2*DINNER*DMOD, Winl + (size_t)i*2*DINNER*DMOD, DMOD,
            nullptr, pxz, 2*DINNER, 0);

        k_conv<<<(MROWS * DINNER + 255) / 256, 256>>>(
            pxz, conv_W + (size_t)i*DINNER*DCONV, conv_b + (size_t)i*DINNER);

        // dbl partial = xc @ W_x^T  (2048 x 64, K split 4 x 256)
        bgemm<64,64,0><<<dim3(1, MROWS/64, DBLKS), 256, SMSZ(64,64)>>>(
            MROWS, 64, DINNER/DBLKS, xch, xcl, DINNER,
            Wxh + (size_t)i*64*DINNER, Wxl + (size_t)i*64*DINNER, DINNER,
            nullptr, pdblp, 64, MROWS*64);

        // scan (inline delta GEMM + fused partial reduce) -> y planes
        k_scan<<<dim3(DINNER/32, BB), 128>>>(
            pxz, pdblp,
            W_dt + (size_t)i*DINNER*DTRANK, b_dt + (size_t)i*DINNER,
            A_log + (size_t)i*DINNER*NST, Dskip + (size_t)i*DINNER);

        // h += y @ W_out^T  (2048 x 512, K=1024)
        bgemm<64,128,2><<<dim3(DMOD/128, MROWS/64), 256, SMSZ(64,128)>>>(
            MROWS, DMOD, DINNER, yh, yl, DINNER,
            Wouth + (size_t)i*DMOD*DINNER, Woutl + (size_t)i*DMOD*DINNER, DINNER,
            nullptr, ph, DMOD, 0);
    }

    // 4) final LN (fp32 for head)
    k_lnw<0><<<MROWS/8, 256>>>(ph, pln, nullptr, nullptr, fn_g, fn_b);

    // 5) head
    k_head1<<<HKS, 256>>>(pln, hW1, ppart);
    k_head2<<<BB, 128>>>(ppart, hb1, hW2, hb2, (float*)d_out);
}

// round 9
// speedup vs baseline: 2.1192x; 1.0528x over previous
#include <cuda_runtime.h>
#include <cuda_bf16.h>
#include <math.h>
#include <stdint.h>

// ---------------- Problem constants ----------------
#define BB      8
#define SEQLEN  4096
#define CINC    7
#define DMOD    512
#define NLAY    4
#define PLEN    16
#define NPATCH  256
#define NST     16
#define DCONV   4
#define DINNER  1024
#define DTRANK  32
#define MROWS   (BB*NPATCH)    // 2048
#define KPATCH  112
#define KPPAD   128
#define HPRED   96
#define HKS     256
#define KFLAT   (NPATCH*DMOD)  // 131072
#define DBLKS   4

// ---------------- fp32 scratch ----------------
__device__ float g_h   [MROWS*DMOD];
__device__ float g_ln  [MROWS*DMOD];
__device__ float g_xz  [MROWS*2*DINNER];
__device__ float g_dblp[DBLKS*MROWS*64];
__device__ float g_part[HKS*BB*128];

// ---------------- bf16 hi/lo activation planes ----------------
__device__ __nv_bfloat16 g_pnh[MROWS*KPPAD],  g_pnl[MROWS*KPPAD];
__device__ __nv_bfloat16 g_lnh[MROWS*DMOD],   g_lnl[MROWS*DMOD];
__device__ __nv_bfloat16 g_xch[MROWS*DINNER], g_xcl[MROWS*DINNER];
__device__ __nv_bfloat16 g_yh [MROWS*DINNER], g_yl [MROWS*DINNER];

// ---------------- bf16 hi/lo weight planes ----------------
__device__ __nv_bfloat16 g_peWh[DMOD*KPPAD],         g_peWl[DMOD*KPPAD];
__device__ __nv_bfloat16 g_Winh[NLAY*2*DINNER*DMOD], g_Winl[NLAY*2*DINNER*DMOD];
__device__ __nv_bfloat16 g_Wxh [NLAY*64*DINNER],     g_Wxl [NLAY*64*DINNER];
__device__ __nv_bfloat16 g_Wouth[NLAY*DMOD*DINNER],  g_Woutl[NLAY*DMOD*DINNER];

#define NWIN  (NLAY*2*DINNER*DMOD)
#define NWOUT (NLAY*DMOD*DINNER)
#define NWX   (NLAY*64*DINNER)

// =====================================================================
// Helpers
// =====================================================================
static __device__ __forceinline__ uint32_t smem_u32(const void* p) {
    uint32_t a;
    asm("{ .reg .u64 t; cvta.to.shared.u64 t, %1; cvt.u32.u64 %0, t; }"
        : "=r"(a) : "l"(p));
    return a;
}
static __device__ __forceinline__ void ldm_x4(uint32_t* r, uint32_t addr) {
    asm volatile("ldmatrix.sync.aligned.m8n8.x4.shared.b16 {%0,%1,%2,%3}, [%4];"
        : "=r"(r[0]), "=r"(r[1]), "=r"(r[2]), "=r"(r[3]) : "r"(addr));
}
static __device__ __forceinline__ void mma_bf16(float* c, const uint32_t* a,
                                                const uint32_t* b) {
    asm volatile(
        "mma.sync.aligned.m16n8k16.row.col.f32.bf16.bf16.f32 "
        "{%0,%1,%2,%3}, {%4,%5,%6,%7}, {%8,%9}, {%0,%1,%2,%3};"
        : "+f"(c[0]), "+f"(c[1]), "+f"(c[2]), "+f"(c[3])
        : "r"(a[0]), "r"(a[1]), "r"(a[2]), "r"(a[3]), "r"(b[0]), "r"(b[1]));
}
static __device__ __forceinline__ void cp16(uint32_t dst, const void* src) {
    asm volatile("cp.async.cg.shared.global [%0], [%1], 16;"
                 :: "r"(dst), "l"(src));
}
static __device__ __forceinline__ void cp_commit() {
    asm volatile("cp.async.commit_group;");
}
template<int NW> static __device__ __forceinline__ void cp_wait() {
    asm volatile("cp.async.wait_group %0;" :: "n"(NW));
}
static __device__ __forceinline__ void split1(float v, __nv_bfloat16& h, __nv_bfloat16& l) {
    h = __float2bfloat16(v);
    l = __float2bfloat16(v - __bfloat162float(h));
}
static __device__ __forceinline__ uint32_t pk2(__nv_bfloat16 a, __nv_bfloat16 b) {
    return (uint32_t)__bfloat16_as_ushort(a) | ((uint32_t)__bfloat16_as_ushort(b) << 16);
}
static __device__ __forceinline__ void split4v(float4 v, uint2& h, uint2& l) {
    __nv_bfloat16 h0,l0,h1,l1,h2,l2,h3,l3;
    split1(v.x,h0,l0); split1(v.y,h1,l1); split1(v.z,h2,l2); split1(v.w,h3,l3);
    h = make_uint2(pk2(h0,h1), pk2(h2,h3));
    l = make_uint2(pk2(l0,l1), pk2(l2,l3));
}
// 16B-unit XOR swizzle for 64B rows: unit u ^= (row>>1)&3
static __device__ __forceinline__ uint32_t swz64(int row, int u) {
    return (uint32_t)(row * 64 + ((u ^ ((row >> 1) & 3)) << 4));
}

// =====================================================================
// Weight split kernels (two launches, also aligns ncu -s window)
// =====================================================================
__global__ void __launch_bounds__(256)
k_splitw(const float* __restrict__ Win, const float* __restrict__ Wx,
         const float* __restrict__ Wout)
{
    const int t0 = blockIdx.x * blockDim.x + threadIdx.x;
    const int stride = gridDim.x * blockDim.x;
    constexpr int T1 = NWIN / 4;
    constexpr int T2 = T1 + NWOUT / 4;
    constexpr int T3 = T2 + NWX / 4;
    for (int i4 = t0; i4 < T3; i4 += stride) {
        const float* src; __nv_bfloat16 *dh, *dl; int off;
        if (i4 < T1)      { src = Win;  dh = g_Winh;  dl = g_Winl;  off = i4; }
        else if (i4 < T2) { src = Wout; dh = g_Wouth; dl = g_Woutl; off = i4 - T1; }
        else              { src = Wx;   dh = g_Wxh;   dl = g_Wxl;   off = i4 - T2; }
        float4 v = *(const float4*)&src[(size_t)off * 4];
        uint2 h, l; split4v(v, h, l);
        *(uint2*)&dh[(size_t)off * 4] = h;
        *(uint2*)&dl[(size_t)off * 4] = l;
    }
}
__global__ void __launch_bounds__(256)
k_splitpe(const float* __restrict__ peW)
{
    const int t0 = blockIdx.x * blockDim.x + threadIdx.x;
    const int stride = gridDim.x * blockDim.x;
    for (int i4 = t0; i4 < DMOD * (KPATCH / 4); i4 += stride) {
        int r = i4 / (KPATCH / 4), c4 = i4 % (KPATCH / 4);
        float4 v = *(const float4*)&peW[(size_t)r * KPATCH + c4 * 4];
        uint2 h, l; split4v(v, h, l);
        *(uint2*)&g_peWh[(size_t)r * KPPAD + c4 * 4] = h;
        *(uint2*)&g_peWl[(size_t)r * KPPAD + c4 * 4] = l;
    }
}

// =====================================================================
// bf16x3 mma.sync GEMM v3: swizzled SMEM (LDS=32), 3-stage cp.async.
// =====================================================================
template<int BM, int BN, int EPI>
__global__ void __launch_bounds__(256, 2)
bgemm(int M, int N, int Ks,
      const __nv_bfloat16* __restrict__ Ah, const __nv_bfloat16* __restrict__ Al, int lda,
      const __nv_bfloat16* __restrict__ Wh, const __nv_bfloat16* __restrict__ Wl, int ldw,
      const float* __restrict__ bias, float* __restrict__ C, int ldc, int sliceC)
{
    constexpr int WNW = (BM == 128) ? 2 : 4;
    constexpr int WN  = BN / WNW;
    constexpr int NT8 = WN / 8;
    constexpr int APLB = BM * 64;          // bytes per plane (32 halves/row)
    constexpr int WPLB = BN * 64;
    constexpr int STGB = 2 * APLB + 2 * WPLB;

    extern __shared__ __nv_bfloat16 sm[];
    const uint32_t smu = smem_u32(sm);

    const int tid = threadIdx.x, lane = tid & 31, warp = tid >> 5;
    const int wn = warp % WNW, wm = warp / WNW;
    const int mB = blockIdx.y * BM, nB = blockIdx.x * BN;
    const int kbase = blockIdx.z * Ks;
    float* pC = C + (size_t)blockIdx.z * sliceC;

    float acc[2][NT8][4];
    #pragma unroll
    for (int t = 0; t < 2; t++)
        #pragma unroll
        for (int j = 0; j < NT8; j++)
            #pragma unroll
            for (int r = 0; r < 4; r++) acc[t][j][r] = 0.f;

    const int nCh = Ks / 32;

    auto load_stage = [&](int s) {
        const uint32_t sb = smu + (uint32_t)((s % 3) * STGB);
        const int k0 = kbase + s * 32;
        #pragma unroll
        for (int i = tid; i < BM * 4; i += 256) {
            int row = i >> 2, u = i & 3;
            size_t g = (size_t)(mB + row) * lda + k0 + u * 8;
            uint32_t d = sb + swz64(row, u);
            cp16(d, Ah + g);
            cp16(d + APLB, Al + g);
        }
        #pragma unroll
        for (int i = tid; i < BN * 4; i += 256) {
            int row = i >> 2, u = i & 3;
            size_t g = (size_t)(nB + row) * ldw + k0 + u * 8;
            uint32_t d = sb + 2 * APLB + swz64(row, u);
            cp16(d, Wh + g);
            cp16(d + WPLB, Wl + g);
        }
        cp_commit();
    };

    load_stage(0);
    if (nCh > 1) load_stage(1); else cp_commit();

    for (int s = 0; s < nCh; s++) {
        if (s + 2 < nCh) load_stage(s + 2); else cp_commit();
        cp_wait<2>();
        __syncthreads();

        const uint32_t sb = smu + (uint32_t)((s % 3) * STGB);
        #pragma unroll
        for (int k16 = 0; k16 < 2; k16++) {
            uint32_t ah[2][4], al[2][4], wf[NT8][2];
            const int arow = wm * 32 + (lane & 15);
            const int au   = k16 * 2 + (lane >> 4);
            const uint32_t aAddr = sb + swz64(arow, au);
            ldm_x4(ah[0], aAddr);
            ldm_x4(ah[1], aAddr + 16 * 64);

            const int wrow = wn * WN + ((lane >> 4) << 3) + (lane & 7);
            const int wu   = k16 * 2 + ((lane >> 3) & 1);
            const uint32_t wAddr = sb + 2 * APLB + swz64(wrow, wu);
            #pragma unroll
            for (int jp = 0; jp < NT8 / 2; jp++) {
                uint32_t t4[4];
                ldm_x4(t4, wAddr + jp * 16 * 64);
                wf[2*jp][0] = t4[0]; wf[2*jp][1] = t4[1];
                wf[2*jp+1][0] = t4[2]; wf[2*jp+1][1] = t4[3];
            }
            #pragma unroll
            for (int t = 0; t < 2; t++)
                #pragma unroll
                for (int j = 0; j < NT8; j++) mma_bf16(acc[t][j], ah[t], wf[j]);

            ldm_x4(al[0], aAddr + APLB);
            ldm_x4(al[1], aAddr + APLB + 16 * 64);
            #pragma unroll
            for (int t = 0; t < 2; t++)
                #pragma unroll
                for (int j = 0; j < NT8; j++) mma_bf16(acc[t][j], al[t], wf[j]);

            #pragma unroll
            for (int jp = 0; jp < NT8 / 2; jp++) {
                uint32_t t4[4];
                ldm_x4(t4, wAddr + WPLB + jp * 16 * 64);
                wf[2*jp][0] = t4[0]; wf[2*jp][1] = t4[1];
                wf[2*jp+1][0] = t4[2]; wf[2*jp+1][1] = t4[3];
            }
            #pragma unroll
            for (int t = 0; t < 2; t++)
                #pragma unroll
                for (int j = 0; j < NT8; j++) mma_bf16(acc[t][j], ah[t], wf[j]);
        }
        __syncthreads();
    }

    #pragma unroll
    for (int t = 0; t < 2; t++) {
        const int m = mB + wm * 32 + t * 16 + (lane >> 2);
        #pragma unroll
        for (int j = 0; j < NT8; j++) {
            const int n = nB + wn * WN + j * 8 + (lane & 3) * 2;
            float2 v0 = make_float2(acc[t][j][0], acc[t][j][1]);
            float2 v1 = make_float2(acc[t][j][2], acc[t][j][3]);
            if (EPI == 1) {
                float b0 = bias[n], b1 = bias[n + 1];
                v0.x += b0; v0.y += b1; v1.x += b0; v1.y += b1;
            }
            if (EPI == 2) {
                float2 p0 = *(const float2*)&pC[(size_t)m * ldc + n];
                float2 p1 = *(const float2*)&pC[(size_t)(m + 8) * ldc + n];
                v0.x += p0.x; v0.y += p0.y; v1.x += p1.x; v1.y += p1.y;
            }
            *(float2*)&pC[(size_t)m * ldc + n]       = v0;
            *(float2*)&pC[(size_t)(m + 8) * ldc + n] = v1;
        }
    }
}

// =====================================================================
// Input layernorm (CIN=7) + patch layout
// =====================================================================
__global__ void k_patchnorm(const float* __restrict__ x,
                            const float* __restrict__ gam,
                            const float* __restrict__ bet)
{
    int idx = blockIdx.x * blockDim.x + threadIdx.x;
    if (idx >= BB * SEQLEN) return;
    int b = idx / SEQLEN, s = idx % SEQLEN;
    const float* xp = x + idx * CINC;
    float sum = 0.f;
    #pragma unroll
    for (int c = 0; c < CINC; c++) sum += xp[c];
    float m = sum * (1.f / CINC);
    float var = 0.f;
    #pragma unroll
    for (int c = 0; c < CINC; c++) { float d = xp[c] - m; var = fmaf(d, d, var); }
    var *= (1.f / CINC);
    float inv = rsqrtf(var + 1e-5f);
    int n = s / PLEN, p = s % PLEN;
    size_t ro = (size_t)(b * NPATCH + n) * KPPAD;
    #pragma unroll
    for (int c = 0; c < CINC; c++) {
        float v = (xp[c] - m) * inv * gam[c] + bet[c];
        __nv_bfloat16 h, l; split1(v, h, l);
        g_pnh[ro + c * PLEN + p] = h;
        g_pnl[ro + c * PLEN + p] = l;
    }
}

// =====================================================================
// Warp-per-row layernorm (width 512)
// =====================================================================
template<int SPLIT>
__global__ void __launch_bounds__(256)
k_lnw(const float* __restrict__ in, float* __restrict__ outf,
      __nv_bfloat16* __restrict__ oh, __nv_bfloat16* __restrict__ ol,
      const float* __restrict__ gam, const float* __restrict__ bet)
{
    const int row  = blockIdx.x * 8 + (threadIdx.x >> 5);
    const int lane = threadIdx.x & 31;
    const float* x = in + (size_t)row * DMOD;

    float4 v[4];
    float s = 0.f, ss = 0.f;
    #pragma unroll
    for (int i = 0; i < 4; i++) {
        v[i] = *(const float4*)&x[i * 128 + lane * 4];
        s  += v[i].x + v[i].y + v[i].z + v[i].w;
        ss += v[i].x*v[i].x + v[i].y*v[i].y + v[i].z*v[i].z + v[i].w*v[i].w;
    }
    #pragma unroll
    for (int o = 16; o > 0; o >>= 1) {
        s  += __shfl_xor_sync(0xffffffffu, s,  o);
        ss += __shfl_xor_sync(0xffffffffu, ss, o);
    }
    float m   = s * (1.f / DMOD);
    float var = ss * (1.f / DMOD) - m * m;
    float inv = rsqrtf(var + 1e-5f);

    #pragma unroll
    for (int i = 0; i < 4; i++) {
        int c = i * 128 + lane * 4;
        float4 g = *(const float4*)&gam[c];
        float4 bb = *(const float4*)&bet[c];
        float o0 = (v[i].x - m) * inv * g.x + bb.x;
        float o1 = (v[i].y - m) * inv * g.y + bb.y;
        float o2 = (v[i].z - m) * inv * g.z + bb.z;
        float o3 = (v[i].w - m) * inv * g.w + bb.w;
        if (SPLIT) {
            float4 vv = make_float4(o0, o1, o2, o3);
            uint2 h, l; split4v(vv, h, l);
            size_t off = (size_t)row * DMOD + c;
            *(uint2*)&oh[off] = h;
            *(uint2*)&ol[off] = l;
        } else {
            *(float4*)&outf[(size_t)row * DMOD + c] = make_float4(o0, o1, o2, o3);
        }
    }
}

// =====================================================================
// Depthwise causal conv (DC=4) + silu -> bf16 hi/lo planes
// =====================================================================
__global__ void k_conv(const float* __restrict__ xz,
                       const float* __restrict__ cw,
                       const float* __restrict__ cb)
{
    int idx = blockIdx.x * blockDim.x + threadIdx.x;
    if (idx >= MROWS * DINNER) return;
    int d  = idx % DINNER;
    int bl = idx / DINNER;
    int l  = bl % NPATCH;
    int b  = bl / NPATCH;
    const float4 w = *(const float4*)(cw + d * 4);
    float acc = cb[d];
    size_t base = (size_t)(b * NPATCH) * 2 * DINNER + d;
    if (l >= 3) acc = fmaf(xz[base + (size_t)(l - 3) * 2 * DINNER], w.x, acc);
    if (l >= 2) acc = fmaf(xz[base + (size_t)(l - 2) * 2 * DINNER], w.y, acc);
    if (l >= 1) acc = fmaf(xz[base + (size_t)(l - 1) * 2 * DINNER], w.z, acc);
    acc = fmaf(xz[base + (size_t)l * 2 * DINNER], w.w, acc);
    float v = acc / (1.f + __expf(-acc));
    __nv_bfloat16 h, lo; split1(v, h, lo);
    g_xch[idx] = h; g_xcl[idx] = lo;
}

// =====================================================================
// Selective scan + inline delta GEMM + fused dbl split-K reduce + gating
// =====================================================================
__global__ void __launch_bounds__(128)
k_scan(const float* __restrict__ xz,  const float* __restrict__ dblp,
       const float* __restrict__ Wdt, const float* __restrict__ bdt,
       const float* __restrict__ A_log, const float* __restrict__ Dskip)
{
    const int tid  = threadIdx.x;
    const int ng   = tid & 3;
    const int dloc = tid >> 2;
    const int d    = blockIdx.x * 32 + dloc;
    const int b    = blockIdx.y;

    __shared__ float sdbl[16][64];
    __shared__ float swdt[32][33];

    {
        int r = tid >> 2, c0 = (tid & 3) * 8;
        #pragma unroll
        for (int j = 0; j < 8; j++)
            swdt[r][c0 + j] = Wdt[(blockIdx.x * 32 + r) * DTRANK + c0 + j];
    }
    const float bv = bdt[d];

    float a[4];
    bool structured = true;
    #pragma unroll
    for (int i = 0; i < 4; i++) {
        int n = ng * 4 + i;
        a[i] = -__expf(A_log[d * NST + n]);
        structured = structured && (fabsf(a[i] + (float)(n + 1)) <= 1e-4f * (float)(n + 1));
    }
    const float Dv = Dskip[d];
    float h[4] = {0.f, 0.f, 0.f, 0.f};

    for (int tt = 0; tt < NPATCH; tt += 16) {
        __syncthreads();
        #pragma unroll
        for (int q = 0; q < 2; q++) {
            int f4 = tid + q * 128;
            int r = f4 >> 4, c4 = f4 & 15;
            size_t gi = (size_t)(b * NPATCH + tt + r) * 64 + c4 * 4;
            float4 v0 = *(const float4*)&dblp[gi];
            float4 v1 = *(const float4*)&dblp[gi + (size_t)MROWS * 64];
            float4 v2 = *(const float4*)&dblp[gi + (size_t)2 * MROWS * 64];
            float4 v3 = *(const float4*)&dblp[gi + (size_t)3 * MROWS * 64];
            *(float4*)&sdbl[r][c4 * 4] = make_float4(
                v0.x + v1.x + v2.x + v3.x, v0.y + v1.y + v2.y + v3.y,
                v0.z + v1.z + v2.z + v3.z, v0.w + v1.w + v2.w + v3.w);
        }
        __syncthreads();

        const int row0 = b * NPATCH + tt;
        float xch_c = __bfloat162float(g_xch[(size_t)row0 * DINNER + d]);
        float xcl_c = __bfloat162float(g_xcl[(size_t)row0 * DINNER + d]);
        float zv_c  = xz[(size_t)row0 * 2 * DINNER + DINNER + d];

        #pragma unroll 4
        for (int t2 = 0; t2 < 16; t2++) {
            float xch_n = 0.f, xcl_n = 0.f, zv_n = 0.f;
            if (t2 < 15) {
                size_t r1 = (size_t)(row0 + t2 + 1);
                xch_n = __bfloat162float(g_xch[r1 * DINNER + d]);
                xcl_n = __bfloat162float(g_xcl[r1 * DINNER + d]);
                zv_n  = xz[r1 * 2 * DINNER + DINNER + d];
            }

            float dot = 0.f;
            #pragma unroll
            for (int j = 0; j < 8; j++)
                dot = fmaf(sdbl[t2][ng * 8 + j], swdt[dloc][ng * 8 + j], dot);
            dot += __shfl_xor_sync(0xffffffffu, dot, 1);
            dot += __shfl_xor_sync(0xffffffffu, dot, 2);
            float xv = dot + bv;

            float q, delta;
            if (xv > 0.f) {
                float e = __expf(-xv);
                q = e / (1.f + e);
                delta = xv + __logf(1.f + e);
            } else {
                float e = __expf(xv);
                q = 1.f / (1.f + e);
                delta = __logf(1.f + e);
            }

            float pw[4];
            if (structured) {
                float q2 = q * q, q4 = q2 * q2;
                float b1 = (ng & 1) ? q4 : 1.f;
                float b2 = (ng & 2) ? q4 * q4 : 1.f;
                float bs = b1 * b2;
                pw[0] = bs * q;      pw[1] = bs * q2;
                pw[2] = bs * q2 * q; pw[3] = bs * q4;
            } else {
                #pragma unroll
                for (int i = 0; i < 4; i++) pw[i] = __expf(delta * a[i]);
            }

            float xcv = xch_c + xcl_c;
            float dx = delta * xcv;
            float acc = 0.f;
            #pragma unroll
            for (int i = 0; i < 4; i++) {
                int n = ng * 4 + i;
                h[i] = fmaf(pw[i], h[i], dx * sdbl[t2][32 + n]);
                acc  = fmaf(h[i], sdbl[t2][48 + n], acc);
            }
            acc += __shfl_xor_sync(0xffffffffu, acc, 1);
            acc += __shfl_xor_sync(0xffffffffu, acc, 2);
            if (ng == 0) {
                float sz = zv_c / (1.f + __expf(-zv_c));
                float yv = (acc + xcv * Dv) * sz;
                __nv_bfloat16 hh, ll; split1(yv, hh, ll);
                size_t di = (size_t)(row0 + t2) * DINNER + d;
                g_yh[di] = hh; g_yl[di] = ll;
            }
            xch_c = xch_n; xcl_c = xcl_n; zv_c = zv_n;
        }
    }
}

// =====================================================================
// Head GEMM1: 256 split-K blocks, coalesced W staging
// =====================================================================
__global__ void __launch_bounds__(256)
k_head1(const float* __restrict__ hin, const float* __restrict__ W,
        float* __restrict__ part)
{
    const int z = blockIdx.x;
    const int kbase = z * (KFLAT / HKS);
    const int tid = threadIdx.x;
    const int j = tid & 127, g = tid >> 7;
    __shared__ float shw[128][65];
    __shared__ float shh[8][65];
    float acc[4] = {0.f, 0.f, 0.f, 0.f};

    for (int kc = 0; kc < KFLAT / HKS; kc += 64) {
        const int k0 = kbase + kc;
        #pragma unroll
        for (int i = tid; i < 128 * 16; i += 256) {
            int r = i >> 4, c4 = i & 15;
            float4 v = *(const float4*)&W[(size_t)r * KFLAT + k0 + c4 * 4];
            shw[r][c4*4+0] = v.x; shw[r][c4*4+1] = v.y;
            shw[r][c4*4+2] = v.z; shw[r][c4*4+3] = v.w;
        }
        if (tid < 128) {
            int r = tid >> 4, c4 = tid & 15;
            float4 v = *(const float4*)&hin[(size_t)r * KFLAT + k0 + c4 * 4];
            shh[r][c4*4+0] = v.x; shh[r][c4*4+1] = v.y;
            shh[r][c4*4+2] = v.z; shh[r][c4*4+3] = v.w;
        }
        __syncthreads();
        #pragma unroll 8
        for (int kk = 0; kk < 64; kk++) {
            float w = shw[j][kk];
            #pragma unroll
            for (int bq = 0; bq < 4; bq++)
                acc[bq] = fmaf(w, shh[g * 4 + bq][kk], acc[bq]);
        }
        __syncthreads();
    }
    #pragma unroll
    for (int bq = 0; bq < 4; bq++)
        part[(size_t)z * (BB * 128) + (g * 4 + bq) * 128 + j] = acc[bq];
}

__global__ void __launch_bounds__(128)
k_head2(const float* __restrict__ part, const float* __restrict__ hb1,
        const float* __restrict__ hW2,  const float* __restrict__ hb2,
        float* __restrict__ out)
{
    const int b = blockIdx.x;
    const int tid = threadIdx.x;
    __shared__ float g[128];
    float v = 0.f;
    for (int z = 0; z < HKS; z++)
        v += part[(size_t)z * (BB * 128) + b * 128 + tid];
    v += hb1[tid];
    g[tid] = 0.5f * v * (1.f + erff(v * 0.70710678118654752f));
    __syncthreads();
    if (tid < HPRED) {
        float acc = hb2[tid];
        #pragma unroll 16
        for (int j = 0; j < 128; j++)
            acc = fmaf(g[j], hW2[tid * 128 + j], acc);
        out[b * HPRED + tid] = acc;
    }
}

// =====================================================================
// Launch
// =====================================================================
static void* symaddr(const void* sym)
{
    void* p = nullptr;
    cudaGetSymbolAddress(&p, sym);
    return p;
}

#define STGBYTES(BM, BN) (2 * (BM) * 64 + 2 * (BN) * 64)
#define SMSZ(BM, BN) (3 * STGBYTES(BM, BN))

extern "C" void kernel_launch(void* const* d_in, const int* in_sizes, int n_in,
                              void* d_out, int out_size)
{
    const float* x      = (const float*)d_in[0];
    const float* in_g   = (const float*)d_in[1];
    const float* in_b   = (const float*)d_in[2];
    const float* pe_W   = (const float*)d_in[3];
    const float* pe_b   = (const float*)d_in[4];
    const float* ln_g   = (const float*)d_in[5];
    const float* ln_b   = (const float*)d_in[6];
    const float* W_in   = (const float*)d_in[7];
    const float* conv_W = (const float*)d_in[8];
    const float* conv_b = (const float*)d_in[9];
    const float* W_x    = (const float*)d_in[10];
    const float* W_dt   = (const float*)d_in[11];
    const float* b_dt   = (const float*)d_in[12];
    const float* A_log  = (const float*)d_in[13];
    const float* Dskip  = (const float*)d_in[14];
    const float* W_out  = (const float*)d_in[15];
    const float* fn_g   = (const float*)d_in[16];
    const float* fn_b   = (const float*)d_in[17];
    const float* hW1    = (const float*)d_in[18];
    const float* hb1    = (const float*)d_in[19];
    const float* hW2    = (const float*)d_in[20];
    const float* hb2    = (const float*)d_in[21];

    float* ph    = (float*)symaddr(g_h);
    float* pln   = (float*)symaddr(g_ln);
    float* pxz   = (float*)symaddr(g_xz);
    float* pdblp = (float*)symaddr(g_dblp);
    float* ppart = (float*)symaddr(g_part);

    __nv_bfloat16* pnh = (__nv_bfloat16*)symaddr(g_pnh);
    __nv_bfloat16* pnl = (__nv_bfloat16*)symaddr(g_pnl);
    __nv_bfloat16* lnh = (__nv_bfloat16*)symaddr(g_lnh);
    __nv_bfloat16* lnl = (__nv_bfloat16*)symaddr(g_lnl);
    __nv_bfloat16* xch = (__nv_bfloat16*)symaddr(g_xch);
    __nv_bfloat16* xcl = (__nv_bfloat16*)symaddr(g_xcl);
    __nv_bfloat16* yh  = (__nv_bfloat16*)symaddr(g_yh);
    __nv_bfloat16* yl  = (__nv_bfloat16*)symaddr(g_yl);

    __nv_bfloat16* peWh = (__nv_bfloat16*)symaddr(g_peWh);
    __nv_bfloat16* peWl = (__nv_bfloat16*)symaddr(g_peWl);
    __nv_bfloat16* Winh = (__nv_bfloat16*)symaddr(g_Winh);
    __nv_bfloat16* Winl = (__nv_bfloat16*)symaddr(g_Winl);
    __nv_bfloat16* Wxh  = (__nv_bfloat16*)symaddr(g_Wxh);
    __nv_bfloat16* Wxl  = (__nv_bfloat16*)symaddr(g_Wxl);
    __nv_bfloat16* Wouth= (__nv_bfloat16*)symaddr(g_Wouth);
    __nv_bfloat16* Woutl= (__nv_bfloat16*)symaddr(g_Woutl);

    static bool attr_done = false;
    if (!attr_done) {
        cudaFuncSetAttribute(bgemm<128,128,0>, cudaFuncAttributeMaxDynamicSharedMemorySize, SMSZ(128,128));
        cudaFuncSetAttribute(bgemm<64,128,1>,  cudaFuncAttributeMaxDynamicSharedMemorySize, SMSZ(64,128));
        cudaFuncSetAttribute(bgemm<64,128,2>,  cudaFuncAttributeMaxDynamicSharedMemorySize, SMSZ(64,128));
        cudaFuncSetAttribute(bgemm<64,64,0>,   cudaFuncAttributeMaxDynamicSharedMemorySize, SMSZ(64,64));
        attr_done = true;
    }

    // 0) weight splits (2 launches; aligns ncu -s 5 window onto W_in bgemm)
    k_splitw<<<1024, 256>>>(W_in, W_x, W_out);
    k_splitpe<<<64, 256>>>(pe_W);

    // 1) input LN + patch planes
    k_patchnorm<<<(BB * SEQLEN + 255) / 256, 256>>>(x, in_g, in_b);

    // 2) patch embed (2048x512, K=128 padded)
    bgemm<64,128,1><<<dim3(DMOD/128, MROWS/64), 256, SMSZ(64,128)>>>(
        MROWS, DMOD, KPPAD, pnh, pnl, KPPAD, peWh, peWl, KPPAD, pe_b, ph, DMOD, 0);

    // 3) Mamba layers
    for (int i = 0; i < NLAY; i++) {
        k_lnw<1><<<MROWS/8, 256>>>(ph, nullptr, lnh, lnl,
                                   ln_g + i * DMOD, ln_b + i * DMOD);

        // xz = ln @ W_in^T  (2048 x 2048, K=512)
        bgemm<128,128,0><<<dim3(2*DINNER/128, MROWS/128), 256, SMSZ(128,128)>>>(
            MROWS, 2*DINNER, DMOD, lnh, lnl, DMOD,
            Winh + (size_t)i*2*DINNER*DMOD, Winl + (size_t)i*2*DINNER*DMOD, DMOD,
            nullptr, pxz, 2*DINNER, 0);

        k_conv<<<(MROWS * DINNER + 255) / 256, 256>>>(
            pxz, conv_W + (size_t)i*DINNER*DCONV, conv_b + (size_t)i*DINNER);

        // dbl partial = xc @ W_x^T  (2048 x 64, K split 4 x 256)
        bgemm<64,64,0><<<dim3(1, MROWS/64, DBLKS), 256, SMSZ(64,64)>>>(
            MROWS, 64, DINNER/DBLKS, xch, xcl, DINNER,
            Wxh + (size_t)i*64*DINNER, Wxl + (size_t)i*64*DINNER, DINNER,
            nullptr, pdblp, 64, MROWS*64);

        // scan (inline delta GEMM + fused partial reduce) -> y planes
        k_scan<<<dim3(DINNER/32, BB), 128>>>(
            pxz, pdblp,
            W_dt + (size_t)i*DINNER*DTRANK, b_dt + (size_t)i*DINNER,
            A_log + (size_t)i*DINNER*NST, Dskip + (size_t)i*DINNER);

        // h += y @ W_out^T  (2048 x 512, K=1024)
        bgemm<64,128,2><<<dim3(DMOD/128, MROWS/64), 256, SMSZ(64,128)>>>(
            MROWS, DMOD, DINNER, yh, yl, DINNER,
            Wouth + (size_t)i*DMOD*DINNER, Woutl + (size_t)i*DMOD*DINNER, DINNER,
            nullptr, ph, DMOD, 0);
    }

    // 4) final LN (fp32 for head)
    k_lnw<0><<<MROWS/8, 256>>>(ph, pln, nullptr, nullptr, fn_g, fn_b);

    // 5) head
    k_head1<<<HKS, 256>>>(pln, hW1, ppart);
    k_head2<<<BB, 128>>>(ppart, hb1, hW2, hb2, (float*)d_out);
}